// round 3
// baseline (speedup 1.0000x reference)
#include <cuda_runtime.h>
#include <stdint.h>

// Problem shape (fixed by setup_inputs)
#define BB 8
#define PP 2048
#define CC 1024
#define KK 3

// Output layout (floats), concatenated in reference return order:
// centers*m [B,P,3], features*m [B,P,C], cls_preds*m [B,P,3], keep [B,P]
#define OFF_CTR  0
#define OFF_FEAT (BB*PP*3)
#define OFF_CLS  (OFF_FEAT + BB*PP*CC)
#define OFF_KEEP (OFF_CLS + BB*PP*3)

#define TA 256  // threads for NMS kernel

__device__ unsigned char g_keep[BB*PP];

// ---------------------------------------------------------------------------
// Kernel A: per-batch greedy NMS.
// Equivalence: global-argmax greedy == descending-score scan keeping any
// point not suppressed by an earlier keeper (suppression is class-local and
// uses the shared per-class radius, so cross-class picks never interact).
// ---------------------------------------------------------------------------
__global__ void __launch_bounds__(TA) nms_kernel(
    const float* __restrict__ centers,
    const float* __restrict__ cls_preds,
    const float* __restrict__ class_radius)
{
    extern __shared__ unsigned char smem[];
    unsigned long long* s_key = (unsigned long long*)smem;          // 16384 B
    float* s_x = (float*)(smem + 16384);                            //  8192 B
    float* s_y = s_x + PP;                                          //  8192 B
    float* s_z = s_y + PP;                                          //  8192 B
    unsigned short* s_orig = (unsigned short*)(s_z + PP);           //  4096 B
    unsigned char* s_lab   = (unsigned char*)(s_orig + PP);         //  2048 B
    unsigned char* s_alive = s_lab + PP;                            //  2048 B  (= 49152 total)

    const int b   = blockIdx.x;
    const int tid = threadIdx.x;
    const float* cp = cls_preds + (size_t)b * PP * KK;
    const float* ct = centers   + (size_t)b * PP * 3;

    const float r0 = class_radius[0];
    const float r1 = class_radius[1];
    const float r2 = class_radius[2];

    // Build sort keys: (orderable-score << 32) | ~idx  -> descending sort gives
    // highest score first, ties broken by lowest original index (matches argmax).
    for (int p = tid; p < PP; p += TA) {
        float v0 = cp[p*3 + 0], v1 = cp[p*3 + 1], v2 = cp[p*3 + 2];
        float best = v0;
        if (v1 > best) best = v1;
        if (v2 > best) best = v2;
        unsigned int u = __float_as_uint(best);
        u = (u & 0x80000000u) ? ~u : (u | 0x80000000u);  // monotone float->uint map
        s_key[p] = ((unsigned long long)u << 32) | (unsigned int)(~(unsigned int)p);
        g_keep[b*PP + p] = 0;  // reset (graph replays reuse this global)
    }
    __syncthreads();

    // Bitonic sort, descending, 2048 elements.
    for (int k = 2; k <= PP; k <<= 1) {
        for (int j = k >> 1; j > 0; j >>= 1) {
            for (int i = tid; i < PP; i += TA) {
                int ixj = i ^ j;
                if (ixj > i) {
                    unsigned long long a = s_key[i];
                    unsigned long long c = s_key[ixj];
                    bool desc = ((i & k) == 0);
                    if (desc ? (a < c) : (a > c)) { s_key[i] = c; s_key[ixj] = a; }
                }
            }
            __syncthreads();
        }
    }

    // Gather point data into sorted order.
    for (int s = tid; s < PP; s += TA) {
        int p = (int)(~(unsigned int)s_key[s]);  // recover original index
        s_orig[s] = (unsigned short)p;
        s_x[s] = ct[p*3 + 0];
        s_y[s] = ct[p*3 + 1];
        s_z[s] = ct[p*3 + 2];
        float v0 = cp[p*3 + 0], v1 = cp[p*3 + 1], v2 = cp[p*3 + 2];
        float best = v0; int lab = 0;
        if (v1 > best) { best = v1; lab = 1; }
        if (v2 > best) { best = v2; lab = 2; }
        s_lab[s] = (unsigned char)lab;
        s_alive[s] = 1;
    }
    __syncthreads();

    // Sequential sweep. Between keeper barriers the alive[] array is
    // read-only, so warps may run ahead through skip iterations safely.
    for (int s = 0; s < PP; s++) {
        if (!s_alive[s]) continue;            // uniform read, no writes pending
        if (tid == 0) g_keep[b*PP + s_orig[s]] = 1;
        const int L = s_lab[s];
        const float r = (L == 0) ? r0 : ((L == 1) ? r1 : r2);
        const float xs = s_x[s], ys = s_y[s], zs = s_z[s];
        // Points before s are already dead (kept or suppressed) -> only q > s.
        for (int q = s + 1 + tid; q < PP; q += TA) {
            if (s_alive[q] && s_lab[q] == (unsigned char)L) {
                // Match reference rounding exactly: rn ops, no FMA, IEEE sqrt.
                float dx = __fsub_rn(s_x[q], xs);
                float dy = __fsub_rn(s_y[q], ys);
                float dz = __fsub_rn(s_z[q], zs);
                float d2 = __fadd_rn(__fadd_rn(__fmul_rn(dx, dx), __fmul_rn(dy, dy)),
                                     __fmul_rn(dz, dz));
                if (__fsqrt_rn(d2) < r) s_alive[q] = 0;
            }
        }
        __syncthreads();
    }
}

// ---------------------------------------------------------------------------
// Kernel B: masked feature copy. One block per row (1024 floats = 256 float4,
// one per thread). Dead rows skip the global read entirely (write-only).
// ---------------------------------------------------------------------------
__global__ void __launch_bounds__(256) feat_mask_kernel(
    const float* __restrict__ features, float* __restrict__ out)
{
    const int row = blockIdx.x;          // 0 .. B*P-1
    const int t   = threadIdx.x;         // 0 .. 255
    float4 v = make_float4(0.f, 0.f, 0.f, 0.f);
    if (g_keep[row]) {
        v = ((const float4*)features)[(size_t)row * 256 + t];
    }
    ((float4*)(out + OFF_FEAT))[(size_t)row * 256 + t] = v;
}

// ---------------------------------------------------------------------------
// Kernel C: masked centers + cls_preds + keep floats (small).
// ---------------------------------------------------------------------------
__global__ void __launch_bounds__(256) small_mask_kernel(
    const float* __restrict__ centers, const float* __restrict__ cls_preds,
    float* __restrict__ out)
{
    const int i = blockIdx.x * blockDim.x + threadIdx.x;
    if (i < BB*PP*3) {
        const int pt = i / 3;
        const float m = g_keep[pt] ? 1.f : 0.f;
        out[OFF_CTR + i] = m * centers[i];
        out[OFF_CLS + i] = m * cls_preds[i];
    } else {
        const int j = i - BB*PP*3;
        if (j < BB*PP) out[OFF_KEEP + j] = g_keep[j] ? 1.f : 0.f;
    }
}

extern "C" void kernel_launch(void* const* d_in, const int* in_sizes, int n_in,
                              void* d_out, int out_size)
{
    (void)in_sizes; (void)n_in; (void)out_size;
    const float* centers   = (const float*)d_in[0];
    const float* features  = (const float*)d_in[1];
    const float* cls_preds = (const float*)d_in[2];
    const float* radius    = (const float*)d_in[3];
    float* out = (float*)d_out;

    nms_kernel<<<BB, TA, 49152>>>(centers, cls_preds, radius);
    feat_mask_kernel<<<BB*PP, 256>>>(features, out);
    // centers(49152) + cls(same i range) + keep(16384) -> 65536 threads
    small_mask_kernel<<<(BB*PP*3 + BB*PP) / 256, 256>>>(centers, cls_preds, out);
}

// round 5
// speedup vs baseline: 1.0181x; 1.0181x over previous
#include <cuda_runtime.h>
#include <stdint.h>

#define BB 8
#define PP 2048
#define CC 1024
#define KK 3

// Output layout (floats): centers*m [B,P,3], features*m [B,P,C], cls*m [B,P,3], keep [B,P]
#define OFF_CTR  0
#define OFF_FEAT (BB*PP*3)
#define OFF_CLS  (OFF_FEAT + BB*PP*CC)
#define OFF_KEEP (OFF_CLS + BB*PP*3)

// Scratch (__device__ globals — no allocation)
__device__ float4             g_sorted[BB*PP];     // x,y,z, label bitcast in .w (512 KB)
__device__ unsigned short     g_orig[BB*PP];       // sorted-pos -> original index
__device__ unsigned long long g_mat[BB*PP*32];     // suppression bitmask rows (4 MB)
__device__ float              g_T[KK];             // per-class d2 threshold
__device__ unsigned char      g_keep[BB*PP];

// ---------------------------------------------------------------------------
// Phase 0: per-batch key build + bitonic sort (desc score, ties -> low index),
// gather sorted coords/labels, and (block 0) compute exact sqrt thresholds.
// T(r) = min{x >= 0 : __fsqrt_rn(x) >= r}  so  sqrt_rn(d2) < r  <=>  d2 < T(r).
// ---------------------------------------------------------------------------
__global__ void __launch_bounds__(512) phase0_sort(
    const float* __restrict__ centers,
    const float* __restrict__ cls_preds,
    const float* __restrict__ class_radius)
{
    __shared__ unsigned long long key[PP];
    const int b = blockIdx.x;
    const int tid = threadIdx.x;
    const float* cp = cls_preds + (size_t)b * PP * KK;
    const float* ct = centers   + (size_t)b * PP * 3;

    for (int p = tid; p < PP; p += 512) {
        float v0 = cp[p*3+0], v1 = cp[p*3+1], v2 = cp[p*3+2];
        float best = v0;
        if (v1 > best) best = v1;
        if (v2 > best) best = v2;
        unsigned int u = __float_as_uint(best);
        u = (u & 0x80000000u) ? ~u : (u | 0x80000000u);   // monotone map
        key[p] = ((unsigned long long)u << 32) | (unsigned int)(~(unsigned int)p);
    }
    __syncthreads();

    for (int k = 2; k <= PP; k <<= 1) {
        for (int j = k >> 1; j > 0; j >>= 1) {
            for (int t = tid; t < PP/2; t += 512) {
                int i   = ((t / j) * 2 * j) + (t % j);
                int ixj = i + j;
                unsigned long long a = key[i];
                unsigned long long c = key[ixj];
                bool desc = ((i & k) == 0);
                if (desc ? (a < c) : (a > c)) { key[i] = c; key[ixj] = a; }
            }
            __syncthreads();
        }
    }

    for (int s = tid; s < PP; s += 512) {
        int p = (int)(~(unsigned int)key[s]);
        g_orig[b*PP + s] = (unsigned short)p;
        float v0 = cp[p*3+0], v1 = cp[p*3+1], v2 = cp[p*3+2];
        float best = v0; int lab = 0;
        if (v1 > best) { best = v1; lab = 1; }
        if (v2 > best) { best = v2; lab = 2; }
        float4 f;
        f.x = ct[p*3+0]; f.y = ct[p*3+1]; f.z = ct[p*3+2];
        f.w = __int_as_float(lab);
        g_sorted[b*PP + s] = f;
    }

    if (b == 0 && tid == 0) {
        for (int k = 0; k < KK; k++) {
            float r = class_radius[k];
            float u = 0.f;
            if (r > 0.f) {
                u = __fmul_rn(r, r);
                while (u > 0.f && __fsqrt_rn(u) >= r)
                    u = __uint_as_float(__float_as_uint(u) - 1u);
                while (__fsqrt_rn(u) < r)
                    u = __uint_as_float(__float_as_uint(u) + 1u);
            }
            g_T[k] = u;
        }
    }
}

// ---------------------------------------------------------------------------
// Phase 1: suppression bitmask matrix. 256 blocks x 256 threads.
// block -> (batch, rowblk 0..7, candblk 0..3). Each lane owns one row; the
// 512-candidate slice is broadcast from SMEM. Bit j of row i: same class AND
// d2 < T (exact replacement for sqrt_rn(d2) < r).
// ---------------------------------------------------------------------------
__global__ void __launch_bounds__(256) phase1_matrix()
{
    __shared__ float4 cand[512];
    const int bidx = blockIdx.x;
    const int b      = bidx >> 5;
    const int rem    = bidx & 31;
    const int rowblk = rem >> 2;
    const int cblk   = rem & 3;
    const int candbase = cblk * 512;
    const int tid  = threadIdx.x;
    const int lane = tid & 31;
    const int w    = tid >> 5;

    for (int c = tid; c < 512; c += 256)
        cand[c] = g_sorted[b*PP + candbase + c];

    const int row = rowblk*256 + w*32 + lane;
    const float4 me = g_sorted[b*PP + row];
    const int labi = __float_as_int(me.w);
    const float Ti = g_T[labi];
    __syncthreads();

    unsigned long long* outp = g_mat + ((size_t)(b*PP + row))*32 + cblk*8;
    for (int wd = 0; wd < 8; wd++) {
        unsigned long long acc = 0;
        #pragma unroll 16
        for (int cc = 0; cc < 64; cc++) {
            float4 f = cand[wd*64 + cc];
            float dx = __fsub_rn(f.x, me.x);
            float dy = __fsub_rn(f.y, me.y);
            float dz = __fsub_rn(f.z, me.z);
            float d2 = __fadd_rn(__fadd_rn(__fmul_rn(dx,dx), __fmul_rn(dy,dy)),
                                 __fmul_rn(dz,dz));
            bool p = (__float_as_int(f.w) == labi) && (d2 < Ti);
            acc |= ((unsigned long long)p) << cc;
        }
        outp[wd] = acc;
    }
}

// ---------------------------------------------------------------------------
// Phase 2: warp-serial scan, one warp per batch. Lane l holds mask word l.
// Row words prefetched DSC deep (matrix is L2-resident). The current 64-bit
// window 'cur' is warp-uniform; expensive shfl refresh only on kept rows that
// actually have suppression bits (nz flag computed off-chain at prefetch).
// Writes both g_keep (for output kernels) and the keep floats of d_out.
// ---------------------------------------------------------------------------
#define DSC 16
__global__ void __launch_bounds__(32) phase2_scan(float* __restrict__ out)
{
    const int b = blockIdx.x;
    const int lane = threadIdx.x;
    const unsigned long long* __restrict__ rowp = g_mat + (size_t)b*PP*32;
    const unsigned short* __restrict__ op = g_orig + b*PP;
    unsigned char* __restrict__ kp = g_keep + b*PP;
    float* __restrict__ ko = out + OFF_KEEP + b*PP;

    unsigned long long ring[DSC];
    int oring[DSC];
    unsigned int nzm = 0;
    #pragma unroll
    for (int d = 0; d < DSC; d++) {
        unsigned long long v = rowp[(size_t)d*32 + lane];
        ring[d] = v;
        if (__ballot_sync(0xffffffffu, v != 0ull)) nzm |= (1u << d);
        oring[d] = op[d];
    }

    unsigned long long mask = 0, cur = 0;
    for (int i0 = 0; i0 < PP; i0 += DSC) {
        #pragma unroll
        for (int d = 0; d < DSC; d++) {
            const int i = i0 + d;
            const int w = i >> 6;
            if ((i & 63) == 0) cur = __shfl_sync(0xffffffffu, mask, w);

            unsigned long long row = ring[d];
            bool nzf = (nzm >> d) & 1u;
            int  ov  = oring[d];

            // prefetch replacement
            const int nxt = i + DSC;
            unsigned long long nv = 0; int no = 0;
            if (nxt < PP) { nv = rowp[(size_t)nxt*32 + lane]; no = op[nxt]; }
            ring[d] = nv; oring[d] = no;
            unsigned int nb = __ballot_sync(0xffffffffu, nv != 0ull);
            nzm = nb ? (nzm | (1u << d)) : (nzm & ~(1u << d));

            bool sup = (cur >> (i & 63)) & 1ull;
            if (!sup) {                       // warp-uniform branch
                mask |= row;
                if (nzf) cur |= __shfl_sync(0xffffffffu, row, w);
            }
            if (lane == 0) {
                kp[ov] = sup ? 0 : 1;
                ko[ov] = sup ? 0.f : 1.f;
            }
        }
    }
}

// ---------------------------------------------------------------------------
// Output: masked feature copy (one block per row; dead rows are write-only)
// ---------------------------------------------------------------------------
__global__ void __launch_bounds__(256) feat_mask_kernel(
    const float* __restrict__ features, float* __restrict__ out)
{
    const int row = blockIdx.x;
    const int t   = threadIdx.x;
    float4 v = make_float4(0.f, 0.f, 0.f, 0.f);
    if (g_keep[row]) v = ((const float4*)features)[(size_t)row * 256 + t];
    ((float4*)(out + OFF_FEAT))[(size_t)row * 256 + t] = v;
}

// Masked centers + cls_preds (keep floats already written by phase2).
__global__ void __launch_bounds__(256) small_mask_kernel(
    const float* __restrict__ centers, const float* __restrict__ cls_preds,
    float* __restrict__ out)
{
    const int i = blockIdx.x * blockDim.x + threadIdx.x;
    if (i < BB*PP*3) {
        const int pt = i / 3;
        const float m = g_keep[pt] ? 1.f : 0.f;
        out[OFF_CTR + i] = m * centers[i];
        out[OFF_CLS + i] = m * cls_preds[i];
    }
}

extern "C" void kernel_launch(void* const* d_in, const int* in_sizes, int n_in,
                              void* d_out, int out_size)
{
    (void)in_sizes; (void)n_in; (void)out_size;
    const float* centers   = (const float*)d_in[0];
    const float* features  = (const float*)d_in[1];
    const float* cls_preds = (const float*)d_in[2];
    const float* radius    = (const float*)d_in[3];
    float* out = (float*)d_out;

    phase0_sort<<<BB, 512>>>(centers, cls_preds, radius);
    phase1_matrix<<<256, 256>>>();
    phase2_scan<<<BB, 32>>>(out);
    feat_mask_kernel<<<BB*PP, 256>>>(features, out);
    small_mask_kernel<<<(BB*PP*3 + 255) / 256, 256>>>(centers, cls_preds, out);
}

// round 6
// speedup vs baseline: 4.8937x; 4.8067x over previous
#include <cuda_runtime.h>
#include <stdint.h>

#define BB 8
#define PP 2048
#define CC 1024
#define KK 3

// Output layout (floats): centers*m [B,P,3], features*m [B,P,C], cls*m [B,P,3], keep [B,P]
#define OFF_CTR  0
#define OFF_FEAT (BB*PP*3)
#define OFF_CLS  (OFF_FEAT + BB*PP*CC)
#define OFF_KEEP (OFF_CLS + BB*PP*3)

// Scratch (__device__ globals — no allocation)
__device__ float4             g_sorted[BB*PP];     // x,y,z, label bitcast in .w (512 KB)
__device__ unsigned short     g_orig[BB*PP];       // sorted-pos -> original index
__device__ unsigned long long g_mat[BB*PP*32];     // suppression bitmask rows (4 MB)
__device__ float              g_T[KK];             // per-class d2 threshold
__device__ unsigned char      g_keep[BB*PP];

// ---------------------------------------------------------------------------
// Phase 0: per-batch key build + bitonic sort (desc score, ties -> low index),
// gather sorted coords/labels, and (block 0) compute exact sqrt thresholds.
// T(r) = min{x >= 0 : __fsqrt_rn(x) >= r}  so  sqrt_rn(d2) < r  <=>  d2 < T(r).
// ---------------------------------------------------------------------------
__global__ void __launch_bounds__(512) phase0_sort(
    const float* __restrict__ centers,
    const float* __restrict__ cls_preds,
    const float* __restrict__ class_radius)
{
    __shared__ unsigned long long key[PP];
    const int b = blockIdx.x;
    const int tid = threadIdx.x;
    const float* cp = cls_preds + (size_t)b * PP * KK;
    const float* ct = centers   + (size_t)b * PP * 3;

    for (int p = tid; p < PP; p += 512) {
        float v0 = cp[p*3+0], v1 = cp[p*3+1], v2 = cp[p*3+2];
        float best = v0;
        if (v1 > best) best = v1;
        if (v2 > best) best = v2;
        unsigned int u = __float_as_uint(best);
        u = (u & 0x80000000u) ? ~u : (u | 0x80000000u);   // monotone map
        key[p] = ((unsigned long long)u << 32) | (unsigned int)(~(unsigned int)p);
    }
    __syncthreads();

    for (int k = 2; k <= PP; k <<= 1) {
        for (int j = k >> 1; j > 0; j >>= 1) {
            for (int t = tid; t < PP/2; t += 512) {
                int i   = ((t / j) * 2 * j) + (t % j);
                int ixj = i + j;
                unsigned long long a = key[i];
                unsigned long long c = key[ixj];
                bool desc = ((i & k) == 0);
                if (desc ? (a < c) : (a > c)) { key[i] = c; key[ixj] = a; }
            }
            __syncthreads();
        }
    }

    for (int s = tid; s < PP; s += 512) {
        int p = (int)(~(unsigned int)key[s]);
        g_orig[b*PP + s] = (unsigned short)p;
        float v0 = cp[p*3+0], v1 = cp[p*3+1], v2 = cp[p*3+2];
        float best = v0; int lab = 0;
        if (v1 > best) { best = v1; lab = 1; }
        if (v2 > best) { best = v2; lab = 2; }
        float4 f;
        f.x = ct[p*3+0]; f.y = ct[p*3+1]; f.z = ct[p*3+2];
        f.w = __int_as_float(lab);
        g_sorted[b*PP + s] = f;
    }

    if (b == 0 && tid == 0) {
        for (int k = 0; k < KK; k++) {
            float r = class_radius[k];
            float u = 0.f;
            if (r > 0.f) {
                u = __fmul_rn(r, r);
                while (u > 0.f && __fsqrt_rn(u) >= r)
                    u = __uint_as_float(__float_as_uint(u) - 1u);
                while (__fsqrt_rn(u) < r)
                    u = __uint_as_float(__float_as_uint(u) + 1u);
            }
            g_T[k] = u;
        }
    }
}

// ---------------------------------------------------------------------------
// Phase 1: suppression bitmask matrix. 256 blocks x 256 threads.
// block -> (batch, rowblk 0..7, candblk 0..3). Each lane owns one row; the
// 512-candidate slice is broadcast from SMEM (all lanes read the same entry:
// conflict-free broadcast). Bit j of row i: same class AND d2 < T.
// ---------------------------------------------------------------------------
__global__ void __launch_bounds__(256) phase1_matrix()
{
    __shared__ float4 cand[512];
    const int bidx = blockIdx.x;
    const int b      = bidx >> 5;
    const int rem    = bidx & 31;
    const int rowblk = rem >> 2;
    const int cblk   = rem & 3;
    const int candbase = cblk * 512;
    const int tid  = threadIdx.x;
    const int lane = tid & 31;
    const int w    = tid >> 5;

    for (int c = tid; c < 512; c += 256)
        cand[c] = g_sorted[b*PP + candbase + c];

    const int row = rowblk*256 + w*32 + lane;
    const float4 me = g_sorted[b*PP + row];
    const int labi = __float_as_int(me.w);
    const float Ti = g_T[labi];
    __syncthreads();

    unsigned long long* outp = g_mat + ((size_t)(b*PP + row))*32 + cblk*8;
    for (int wd = 0; wd < 8; wd++) {
        unsigned long long acc = 0;
        #pragma unroll 16
        for (int cc = 0; cc < 64; cc++) {
            float4 f = cand[wd*64 + cc];
            float dx = __fsub_rn(f.x, me.x);
            float dy = __fsub_rn(f.y, me.y);
            float dz = __fsub_rn(f.z, me.z);
            float d2 = __fadd_rn(__fadd_rn(__fmul_rn(dx,dx), __fmul_rn(dy,dy)),
                                 __fmul_rn(dz,dz));
            bool p = (__float_as_int(f.w) == labi) && (d2 < Ti);
            acc |= ((unsigned long long)p) << cc;
        }
        outp[wd] = acc;
    }
}

// ---------------------------------------------------------------------------
// Phase 2: warp-serial scan, one warp per batch. Lane l holds running-mask
// word l. Row words come from a prefetch ring (distance DSC, off the critical
// chain). Critical chain per point: uniform bit-test on cur + (if kept) one
// shfl to fold the keeper's current-word bits into cur. NO ballots, NO
// memory ops, NO serial register updates tied to loads on the chain.
// Keep decisions accumulate in keepw (lane == word index) and are written
// out in a parallel epilogue.
// ---------------------------------------------------------------------------
#define DSC 16
__global__ void __launch_bounds__(32) phase2_scan(float* __restrict__ out)
{
    const int b = blockIdx.x;
    const int lane = threadIdx.x;
    const unsigned long long* __restrict__ rowp = g_mat + (size_t)b*PP*32;
    const unsigned short* __restrict__ op = g_orig + b*PP;
    unsigned char* __restrict__ kp = g_keep + b*PP;
    float* __restrict__ ko = out + OFF_KEEP + b*PP;

    unsigned long long ring[DSC];
    #pragma unroll
    for (int d = 0; d < DSC; d++)
        ring[d] = rowp[(size_t)d*32 + lane];

    unsigned long long mask = 0, cur = 0, keepw = 0;
    for (int i0 = 0; i0 < PP; i0 += DSC) {
        #pragma unroll
        for (int d = 0; d < DSC; d++) {
            const int i = i0 + d;
            const int w = i >> 6;

            unsigned long long row = ring[d];
            // prefetch replacement (not on the decision chain)
            const int nxt = i + DSC;
            ring[d] = (nxt < PP) ? rowp[(size_t)nxt*32 + lane] : 0ull;

            if ((i & 63) == 0) cur = __shfl_sync(0xffffffffu, mask, w);

            bool sup = (cur >> (i & 63)) & 1ull;   // warp-uniform
            if (!sup) {
                mask |= row;
                cur  |= __shfl_sync(0xffffffffu, row, w);
                if (lane == w) keepw |= 1ull << (i & 63);
            }
        }
    }

    // Parallel epilogue: lane l owns keep bits for sorted positions [64l, 64l+64)
    #pragma unroll 8
    for (int bit = 0; bit < 64; bit++) {
        int pos = lane*64 + bit;
        int ov = op[pos];
        bool k = (keepw >> bit) & 1ull;
        kp[ov] = k ? 1 : 0;
        ko[ov] = k ? 1.f : 0.f;
    }
}

// ---------------------------------------------------------------------------
// Output: masked feature copy (one block per row; dead rows are write-only)
// ---------------------------------------------------------------------------
__global__ void __launch_bounds__(256) feat_mask_kernel(
    const float* __restrict__ features, float* __restrict__ out)
{
    const int row = blockIdx.x;
    const int t   = threadIdx.x;
    float4 v = make_float4(0.f, 0.f, 0.f, 0.f);
    if (g_keep[row]) v = ((const float4*)features)[(size_t)row * 256 + t];
    ((float4*)(out + OFF_FEAT))[(size_t)row * 256 + t] = v;
}

// Masked centers + cls_preds (keep floats already written by phase2).
__global__ void __launch_bounds__(256) small_mask_kernel(
    const float* __restrict__ centers, const float* __restrict__ cls_preds,
    float* __restrict__ out)
{
    const int i = blockIdx.x * blockDim.x + threadIdx.x;
    if (i < BB*PP*3) {
        const int pt = i / 3;
        const float m = g_keep[pt] ? 1.f : 0.f;
        out[OFF_CTR + i] = m * centers[i];
        out[OFF_CLS + i] = m * cls_preds[i];
    }
}

extern "C" void kernel_launch(void* const* d_in, const int* in_sizes, int n_in,
                              void* d_out, int out_size)
{
    (void)in_sizes; (void)n_in; (void)out_size;
    const float* centers   = (const float*)d_in[0];
    const float* features  = (const float*)d_in[1];
    const float* cls_preds = (const float*)d_in[2];
    const float* radius    = (const float*)d_in[3];
    float* out = (float*)d_out;

    phase0_sort<<<BB, 512>>>(centers, cls_preds, radius);
    phase1_matrix<<<256, 256>>>();
    phase2_scan<<<BB, 32>>>(out);
    feat_mask_kernel<<<BB*PP, 256>>>(features, out);
    small_mask_kernel<<<(BB*PP*3 + 255) / 256, 256>>>(centers, cls_preds, out);
}

// round 7
// speedup vs baseline: 6.1965x; 1.2662x over previous
#include <cuda_runtime.h>
#include <stdint.h>

#define BB 8
#define PP 2048
#define CC 1024
#define KK 3

// Output layout (floats): centers*m [B,P,3], features*m [B,P,C], cls*m [B,P,3], keep [B,P]
#define OFF_CTR  0
#define OFF_FEAT (BB*PP*3)
#define OFF_CLS  (OFF_FEAT + BB*PP*CC)
#define OFF_KEEP (OFF_CLS + BB*PP*3)

typedef unsigned long long u64;
typedef unsigned int       u32;

// Scratch (__device__ globals — no allocation)
__device__ float4          g_sorted[BB*PP];   // x,y,z, label bitcast in .w
__device__ unsigned short  g_orig[BB*PP];     // sorted-pos -> original index
__device__ u64             g_mat[BB*PP*32];   // suppression bitmask rows (4 MB)
__device__ float           g_T[KK];           // per-class d2 threshold
__device__ unsigned char   g_keep[BB*PP];

// Upper-triangle tile list: (rowblk of 256 rows, candblk of 512 cols) kept iff
// the tile contains any col > row. 20 of 32 tiles per batch.
__constant__ unsigned char c_r[20] = {0,0,0,0, 1,1,1,1, 2,2,2, 3,3,3, 4,4, 5,5, 6, 7};
__constant__ unsigned char c_c[20] = {0,1,2,3, 0,1,2,3, 1,2,3, 1,2,3, 2,3, 2,3, 3, 3};

// ---------------------------------------------------------------------------
// Phase 0: bitonic sort per batch (desc score, ties -> low index), gather
// sorted coords/labels; block 0 computes exact sqrt thresholds:
// T(r) = min{x : __fsqrt_rn(x) >= r}  so  sqrt_rn(d2) < r  <=>  d2 < T(r).
// 1024 threads: one comparator per thread per stage.
// ---------------------------------------------------------------------------
__global__ void __launch_bounds__(1024) phase0_sort(
    const float* __restrict__ centers,
    const float* __restrict__ cls_preds,
    const float* __restrict__ class_radius)
{
    __shared__ u64 key[PP];
    const int b = blockIdx.x;
    const int tid = threadIdx.x;
    const float* cp = cls_preds + (size_t)b * PP * KK;
    const float* ct = centers   + (size_t)b * PP * 3;

    #pragma unroll
    for (int q = 0; q < 2; q++) {
        int p = tid + q*1024;
        float v0 = cp[p*3+0], v1 = cp[p*3+1], v2 = cp[p*3+2];
        float best = v0;
        if (v1 > best) best = v1;
        if (v2 > best) best = v2;
        u32 u = __float_as_uint(best);
        u = (u & 0x80000000u) ? ~u : (u | 0x80000000u);   // monotone map
        key[p] = ((u64)u << 32) | (u32)(~(u32)p);
    }
    __syncthreads();

    for (int k = 2; k <= PP; k <<= 1) {
        for (int j = k >> 1; j > 0; j >>= 1) {
            int low = tid & (j-1);
            int i   = ((tid ^ low) << 1) | low;
            int ixj = i + j;
            u64 a = key[i];
            u64 c = key[ixj];
            bool desc = ((i & k) == 0);
            if (desc ? (a < c) : (a > c)) { key[i] = c; key[ixj] = a; }
            __syncthreads();
        }
    }

    #pragma unroll
    for (int q = 0; q < 2; q++) {
        int s = tid + q*1024;
        int p = (int)(~(u32)key[s]);
        g_orig[b*PP + s] = (unsigned short)p;
        float v0 = cp[p*3+0], v1 = cp[p*3+1], v2 = cp[p*3+2];
        float best = v0; int lab = 0;
        if (v1 > best) { best = v1; lab = 1; }
        if (v2 > best) { best = v2; lab = 2; }
        float4 f;
        f.x = ct[p*3+0]; f.y = ct[p*3+1]; f.z = ct[p*3+2];
        f.w = __int_as_float(lab);
        g_sorted[b*PP + s] = f;
    }

    if (b == 0 && tid == 0) {
        for (int k = 0; k < KK; k++) {
            float r = class_radius[k];
            float u = 0.f;
            if (r > 0.f) {
                u = __fmul_rn(r, r);
                while (u > 0.f && __fsqrt_rn(u) >= r)
                    u = __uint_as_float(__float_as_uint(u) - 1u);
                while (__fsqrt_rn(u) < r)
                    u = __uint_as_float(__float_as_uint(u) + 1u);
            }
            g_T[k] = u;
        }
    }
}

// ---------------------------------------------------------------------------
// Phase 1: suppression bitmask matrix, UPPER-TRIANGLE TILES ONLY.
// 160 blocks x 256 threads; block -> (batch, rowblk, candblk) via table.
// Each lane owns one row; 512-candidate slice broadcast from SMEM.
// ---------------------------------------------------------------------------
__global__ void __launch_bounds__(256) phase1_matrix()
{
    __shared__ float4 cand[512];
    const int bidx = blockIdx.x;
    const int b    = bidx / 20;
    const int t20  = bidx % 20;
    const int rowblk = c_r[t20];
    const int cblk   = c_c[t20];
    const int candbase = cblk * 512;
    const int tid  = threadIdx.x;
    const int lane = tid & 31;
    const int w    = tid >> 5;

    for (int c = tid; c < 512; c += 256)
        cand[c] = g_sorted[b*PP + candbase + c];

    const int row = rowblk*256 + w*32 + lane;
    const float4 me = g_sorted[b*PP + row];
    const int labi = __float_as_int(me.w);
    const float Ti = g_T[labi];
    __syncthreads();

    u64* outp = g_mat + ((size_t)(b*PP + row))*32 + cblk*8;
    for (int wd = 0; wd < 8; wd++) {
        u64 acc = 0;
        #pragma unroll 16
        for (int cc = 0; cc < 64; cc++) {
            float4 f = cand[wd*64 + cc];
            float dx = __fsub_rn(f.x, me.x);
            float dy = __fsub_rn(f.y, me.y);
            float dz = __fsub_rn(f.z, me.z);
            float d2 = __fadd_rn(__fadd_rn(__fmul_rn(dx,dx), __fmul_rn(dy,dy)),
                                 __fmul_rn(dz,dz));
            bool p = (__float_as_int(f.w) == labi) && (d2 < Ti);
            acc |= ((u64)p) << cc;
        }
        outp[wd] = acc;
    }
}

// ---------------------------------------------------------------------------
// Phase 2: one warp per batch. Lane l holds running-mask word l and, via the
// prefetch ring, word l of every row. The 64x64 diagonal block of word w is
// therefore register-local to lane w -> local serial resolve with a pure
// ALU chain (sign-broadcast of alive bit + one LOP3), NO shfl on the chain.
// Words processed as two 32-bit halves; one shfl per half broadcasts keep
// bits; all lanes then OR kept rows into their mask word.
// Only strictly-upper bits of a row influence decisions (lower-triangle /
// uncomputed-tile garbage is confined to already-decided positions).
// ---------------------------------------------------------------------------
__global__ void __launch_bounds__(32) phase2_scan(float* __restrict__ out)
{
    const int b = blockIdx.x;
    const int lane = threadIdx.x;
    const u64* __restrict__ rowp = g_mat + (size_t)b*PP*32;
    const unsigned short* __restrict__ op = g_orig + b*PP;
    unsigned char* __restrict__ kp = g_keep + b*PP;
    float* __restrict__ ko = out + OFF_KEEP + b*PP;

    u64 ring[64];  // [0..31] = half A rows, [32..63] = half B rows of current word
    #pragma unroll
    for (int k = 0; k < 64; k++)
        ring[k] = rowp[(size_t)k*32 + lane];

    u64 mask = 0, keepw = 0;

    #pragma unroll 1
    for (int w = 0; w < 32; w++) {
        // ---------------- half A: bits 0..31 of word w ----------------
        {
            u32 av = ~(u32)mask;          // lane's own lo word; lane w's is live
            u32 kb = 0;
            #pragma unroll
            for (int j = 0; j < 32; j++) {
                u32 rloUp = (u32)ring[j] & ((j < 31) ? (0xFFFFFFFEu << j) : 0u); // strict upper (off-chain)
                u32 m = (u32)(((int)(av << (31 - j))) >> 31);  // all-ones iff bit j alive
                kb |= m & (1u << j);
                av &= ~(m & rloUp);
            }
            kb = __shfl_sync(0xffffffffu, kb, w);
            u64 a0 = 0, a1 = 0, a2 = 0, a3 = 0;
            #pragma unroll
            for (int j = 0; j < 32; j += 4) {
                if (kb & (1u << j))       a0 |= ring[j];
                if (kb & (1u << (j + 1))) a1 |= ring[j + 1];
                if (kb & (1u << (j + 2))) a2 |= ring[j + 2];
                if (kb & (1u << (j + 3))) a3 |= ring[j + 3];
            }
            mask |= (a0 | a1) | (a2 | a3);
            if (lane == w) keepw |= (u64)kb;
            // refill slot A with half (2w+2), i.e. rows (w+1)*64 .. +31
            const int base = (2*w + 2) * 32;
            if (base < PP) {
                #pragma unroll
                for (int k = 0; k < 32; k++)
                    ring[k] = rowp[(size_t)(base + k)*32 + lane];
            }
        }
        // ---------------- half B: bits 32..63 of word w ----------------
        {
            u32 av = ~(u32)(mask >> 32);  // includes half-A keepers' bits
            u32 kb = 0;
            #pragma unroll
            for (int j = 0; j < 32; j++) {
                u32 rhiUp = (u32)(ring[32 + j] >> 32) & ((j < 31) ? (0xFFFFFFFEu << j) : 0u);
                u32 m = (u32)(((int)(av << (31 - j))) >> 31);
                kb |= m & (1u << j);
                av &= ~(m & rhiUp);
            }
            kb = __shfl_sync(0xffffffffu, kb, w);
            u64 a0 = 0, a1 = 0, a2 = 0, a3 = 0;
            #pragma unroll
            for (int j = 0; j < 32; j += 4) {
                if (kb & (1u << j))       a0 |= ring[32 + j];
                if (kb & (1u << (j + 1))) a1 |= ring[32 + j + 1];
                if (kb & (1u << (j + 2))) a2 |= ring[32 + j + 2];
                if (kb & (1u << (j + 3))) a3 |= ring[32 + j + 3];
            }
            mask |= (a0 | a1) | (a2 | a3);
            if (lane == w) keepw |= ((u64)kb) << 32;
            // refill slot B with half (2w+3), i.e. rows (w+1)*64 + 32 .. +63
            const int base = (2*w + 3) * 32;
            if (base < PP) {
                #pragma unroll
                for (int k = 0; k < 32; k++)
                    ring[32 + k] = rowp[(size_t)(base + k)*32 + lane];
            }
        }
    }

    // Parallel epilogue: lane l owns keep bits for sorted positions [64l, 64l+64)
    #pragma unroll 8
    for (int bit = 0; bit < 64; bit++) {
        int pos = lane*64 + bit;
        int ov = op[pos];
        bool k = (keepw >> bit) & 1ull;
        kp[ov] = k ? 1 : 0;
        ko[ov] = k ? 1.f : 0.f;
    }
}

// ---------------------------------------------------------------------------
// Output: masked feature copy (one block per row; dead rows are write-only)
// ---------------------------------------------------------------------------
__global__ void __launch_bounds__(256) feat_mask_kernel(
    const float* __restrict__ features, float* __restrict__ out)
{
    const int row = blockIdx.x;
    const int t   = threadIdx.x;
    float4 v = make_float4(0.f, 0.f, 0.f, 0.f);
    if (g_keep[row]) v = ((const float4*)features)[(size_t)row * 256 + t];
    ((float4*)(out + OFF_FEAT))[(size_t)row * 256 + t] = v;
}

// Masked centers + cls_preds (keep floats already written by phase2).
__global__ void __launch_bounds__(256) small_mask_kernel(
    const float* __restrict__ centers, const float* __restrict__ cls_preds,
    float* __restrict__ out)
{
    const int i = blockIdx.x * blockDim.x + threadIdx.x;
    if (i < BB*PP*3) {
        const int pt = i / 3;
        const float m = g_keep[pt] ? 1.f : 0.f;
        out[OFF_CTR + i] = m * centers[i];
        out[OFF_CLS + i] = m * cls_preds[i];
    }
}

extern "C" void kernel_launch(void* const* d_in, const int* in_sizes, int n_in,
                              void* d_out, int out_size)
{
    (void)in_sizes; (void)n_in; (void)out_size;
    const float* centers   = (const float*)d_in[0];
    const float* features  = (const float*)d_in[1];
    const float* cls_preds = (const float*)d_in[2];
    const float* radius    = (const float*)d_in[3];
    float* out = (float*)d_out;

    phase0_sort<<<BB, 1024>>>(centers, cls_preds, radius);
    phase1_matrix<<<8*20, 256>>>();
    phase2_scan<<<BB, 32>>>(out);
    feat_mask_kernel<<<BB*PP, 256>>>(features, out);
    small_mask_kernel<<<(BB*PP*3 + 255) / 256, 256>>>(centers, cls_preds, out);
}

// round 8
// speedup vs baseline: 9.3943x; 1.5161x over previous
#include <cuda_runtime.h>
#include <stdint.h>

#define BB 8
#define PP 2048
#define CC 1024
#define KK 3
#define NMAX 1024      // per-class capacity (n_k ~ 683 +- 21, >15 sigma safe)
#define WMAX 16        // 64-bit words per matrix row (NMAX/64)

// Output layout (floats): centers*m [B,P,3], features*m [B,P,C], cls*m [B,P,3], keep [B,P]
#define OFF_CTR  0
#define OFF_FEAT (BB*PP*3)
#define OFF_CLS  (OFF_FEAT + BB*PP*CC)
#define OFF_KEEP (OFF_CLS + BB*PP*3)

typedef unsigned long long u64;
typedef unsigned int       u32;

// Scratch (__device__ globals — no allocation)
__device__ float4          g_cpos[BB*KK*NMAX];        // per-class sorted coords
__device__ unsigned short  g_corig[BB*KK*NMAX];       // per-class -> original idx
__device__ int             g_cn[BB*KK];               // per-class counts
__device__ u64             g_cmat[(size_t)BB*KK*NMAX*WMAX];  // 3 MB bitmask
__device__ float           g_T[KK];                   // exact d2 thresholds
__device__ unsigned char   g_keep[BB*PP];

// Upper-triangle 256x256 tiles over NMAX: (rt, ct) with ct >= rt. 10 tiles.
__constant__ unsigned char c_rt[10] = {0,0,0,0, 1,1,1, 2,2, 3};
__constant__ unsigned char c_ct[10] = {0,1,2,3, 1,2,3, 2,3, 3};

// ---------------------------------------------------------------------------
// Phase 0: per-batch — labels/scores, class histogram, bitonic sort ascending
// by key = (label<<44) | (~scoremap<<12) | idx  (=> class-contiguous segments,
// score desc, ties -> low idx), scatter into per-class arrays. Block 0 also
// computes exact thresholds: T(r) = min{x : __fsqrt_rn(x) >= r}, so
// sqrt_rn(d2) < r  <=>  d2 < T(r)  bit-exactly.
// ---------------------------------------------------------------------------
__global__ void __launch_bounds__(1024) phase0_sort(
    const float* __restrict__ centers,
    const float* __restrict__ cls_preds,
    const float* __restrict__ class_radius)
{
    __shared__ u64 key[PP];
    __shared__ int s_cnt[KK];
    __shared__ int s_off[KK];
    const int b = blockIdx.x;
    const int tid = threadIdx.x;
    const float* cp = cls_preds + (size_t)b * PP * KK;
    const float* ct = centers   + (size_t)b * PP * 3;

    if (tid < KK) s_cnt[tid] = 0;
    __syncthreads();

    #pragma unroll
    for (int q = 0; q < 2; q++) {
        int p = tid + q*1024;
        float v0 = cp[p*3+0], v1 = cp[p*3+1], v2 = cp[p*3+2];
        float best = v0; int lab = 0;
        if (v1 > best) { best = v1; lab = 1; }
        if (v2 > best) { best = v2; lab = 2; }
        u32 u = __float_as_uint(best);
        u = (u & 0x80000000u) ? ~u : (u | 0x80000000u);   // monotone map
        atomicAdd(&s_cnt[lab], 1);
        key[p] = ((u64)lab << 44) | ((u64)(~u) << 12) | (u64)p;
    }
    __syncthreads();

    // Bitonic sort ascending, one comparator per thread per stage.
    for (int k = 2; k <= PP; k <<= 1) {
        for (int j = k >> 1; j > 0; j >>= 1) {
            int low = tid & (j-1);
            int i   = ((tid ^ low) << 1) | low;
            int ixj = i + j;
            u64 a = key[i];
            u64 c = key[ixj];
            bool asc = ((i & k) == 0);
            if (asc ? (a > c) : (a < c)) { key[i] = c; key[ixj] = a; }
            __syncthreads();
        }
    }

    if (tid == 0) {
        int o = 0;
        for (int k = 0; k < KK; k++) { s_off[k] = o; o += s_cnt[k]; g_cn[b*KK+k] = s_cnt[k]; }
    }
    __syncthreads();

    #pragma unroll
    for (int q = 0; q < 2; q++) {
        int s = tid + q*1024;
        u64 kk = key[s];
        int lab = (int)(kk >> 44);
        int p   = (int)(kk & 0xFFFu);
        int r   = s - s_off[lab];
        float4 f;
        f.x = ct[p*3+0]; f.y = ct[p*3+1]; f.z = ct[p*3+2]; f.w = 0.f;
        g_cpos [(b*KK+lab)*NMAX + r] = f;
        g_corig[(b*KK+lab)*NMAX + r] = (unsigned short)p;
    }

    if (b == 0 && tid == 0) {
        for (int k = 0; k < KK; k++) {
            float r = class_radius[k];
            float u = 0.f;
            if (r > 0.f) {
                u = __fmul_rn(r, r);
                while (u > 0.f && __fsqrt_rn(u) >= r)
                    u = __uint_as_float(__float_as_uint(u) - 1u);
                while (__fsqrt_rn(u) < r)
                    u = __uint_as_float(__float_as_uint(u) + 1u);
            }
            g_T[k] = u;
        }
    }
}

// ---------------------------------------------------------------------------
// Phase 1: per-class suppression bitmask matrix, upper-triangle 256x256 tiles,
// runtime-clipped to the class size. No label test (class-pure). Rows/cols
// beyond n_k produce garbage bits confined to positions >= n_k (inert).
// ---------------------------------------------------------------------------
__global__ void __launch_bounds__(256) phase1_matrix()
{
    __shared__ float4 cand[256];
    const int bidx = blockIdx.x;
    const int bk = bidx / 10;          // (batch, class) 0..23
    const int t  = bidx % 10;
    const int k  = bk % KK;
    const int n  = g_cn[bk];
    const int nw64 = (n + 63) & ~63;
    const int rowbase  = (int)c_rt[t] * 256;
    const int candbase = (int)c_ct[t] * 256;
    if (rowbase >= n || candbase >= nw64) return;

    const int tid = threadIdx.x;
    const float4* __restrict__ pos = g_cpos + (size_t)bk * NMAX;

    cand[tid] = pos[candbase + tid];
    const float4 me = pos[rowbase + tid];
    const float Ti = g_T[k];
    __syncthreads();

    u64* outp = g_cmat + ((size_t)bk*NMAX + rowbase + tid)*WMAX + (int)c_ct[t]*4;
    #pragma unroll
    for (int wd = 0; wd < 4; wd++) {
        u64 acc = 0;
        #pragma unroll 16
        for (int cc = 0; cc < 64; cc++) {
            float4 f = cand[wd*64 + cc];
            float dx = __fsub_rn(f.x, me.x);
            float dy = __fsub_rn(f.y, me.y);
            float dz = __fsub_rn(f.z, me.z);
            float d2 = __fadd_rn(__fadd_rn(__fmul_rn(dx,dx), __fmul_rn(dy,dy)),
                                 __fmul_rn(dz,dz));
            acc |= ((u64)(d2 < Ti)) << cc;
        }
        outp[wd] = acc;
    }
}

// ---------------------------------------------------------------------------
// Phase 2: one warp per (batch, class) — 24 independent scans. Lane l holds
// running-mask word l (l = lane & 15 for ring loads); the 64x64 diagonal block
// of word w is register-local to lane w -> pure-ALU serial resolve, no shfl
// on the chain; one shfl per 32 points broadcasts keep bits. Chain length
// nw*64 ~= 704 bits instead of 2048.
// ---------------------------------------------------------------------------
__global__ void __launch_bounds__(32) phase2_scan(float* __restrict__ out)
{
    const int bk = blockIdx.x;
    const int b  = bk / KK;
    const int n  = g_cn[bk];
    const int nw = (n + 63) >> 6;
    const int lane = threadIdx.x;
    const int ll = lane & 15;
    const u64* __restrict__ rowp = g_cmat + (size_t)bk*NMAX*WMAX;

    u64 ring[64];  // sliding window: ring[j] = word ll of row (window_base + j)
    #pragma unroll
    for (int j = 0; j < 64; j++)
        ring[j] = rowp[(size_t)j*WMAX + ll];

    u64 mask = 0, keepw = 0;

    #pragma unroll 1
    for (int w = 0; w < nw; w++) {
        // ---------------- half A: bits 0..31 of word w ----------------
        {
            u32 av = ~(u32)mask;          // lane w's copy is the live one
            u32 kb = 0;
            #pragma unroll
            for (int j = 0; j < 32; j++) {
                u32 rloUp = (u32)ring[j] & ((j < 31) ? (0xFFFFFFFEu << j) : 0u);
                u32 m = (u32)(((int)(av << (31 - j))) >> 31);  // bcast of alive bit j
                kb |= m & (1u << j);
                av &= ~(m & rloUp);
            }
            kb = __shfl_sync(0xffffffffu, kb, w);
            u64 a0 = 0, a1 = 0, a2 = 0, a3 = 0;
            #pragma unroll
            for (int j = 0; j < 32; j += 4) {
                if (kb & (1u << j))       a0 |= ring[j];
                if (kb & (1u << (j + 1))) a1 |= ring[j + 1];
                if (kb & (1u << (j + 2))) a2 |= ring[j + 2];
                if (kb & (1u << (j + 3))) a3 |= ring[j + 3];
            }
            mask |= (a0 | a1) | (a2 | a3);
            if (lane == w) keepw |= (u64)kb;
            const int base = (2*w + 2) * 32;   // rows for word (w+1), half A
            if (base < NMAX) {
                #pragma unroll
                for (int j = 0; j < 32; j++)
                    ring[j] = rowp[(size_t)(base + j)*WMAX + ll];
            }
        }
        // ---------------- half B: bits 32..63 of word w ----------------
        {
            u32 av = ~(u32)(mask >> 32);
            u32 kb = 0;
            #pragma unroll
            for (int j = 0; j < 32; j++) {
                u32 rhiUp = (u32)(ring[32 + j] >> 32) & ((j < 31) ? (0xFFFFFFFEu << j) : 0u);
                u32 m = (u32)(((int)(av << (31 - j))) >> 31);
                kb |= m & (1u << j);
                av &= ~(m & rhiUp);
            }
            kb = __shfl_sync(0xffffffffu, kb, w);
            u64 a0 = 0, a1 = 0, a2 = 0, a3 = 0;
            #pragma unroll
            for (int j = 0; j < 32; j += 4) {
                if (kb & (1u << j))       a0 |= ring[32 + j];
                if (kb & (1u << (j + 1))) a1 |= ring[32 + j + 1];
                if (kb & (1u << (j + 2))) a2 |= ring[32 + j + 2];
                if (kb & (1u << (j + 3))) a3 |= ring[32 + j + 3];
            }
            mask |= (a0 | a1) | (a2 | a3);
            if (lane == w) keepw |= ((u64)kb) << 32;
            const int base = (2*w + 3) * 32;   // rows for word (w+1), half B
            if (base < NMAX) {
                #pragma unroll
                for (int j = 0; j < 32; j++)
                    ring[32 + j] = rowp[(size_t)(base + j)*WMAX + ll];
            }
        }
    }

    // Epilogue: lane l owns keep bits for class positions [64l, 64l+64)
    const unsigned short* __restrict__ op = g_corig + (size_t)bk*NMAX;
    unsigned char* __restrict__ kp = g_keep + b*PP;
    float* __restrict__ ko = out + OFF_KEEP + b*PP;
    #pragma unroll 8
    for (int bit = 0; bit < 64; bit++) {
        int pos = lane*64 + bit;
        if (pos < n) {
            int ov = op[pos];
            bool kv = (keepw >> bit) & 1ull;
            kp[ov] = kv ? 1 : 0;
            ko[ov] = kv ? 1.f : 0.f;
        }
    }
}

// ---------------------------------------------------------------------------
// Output: masked feature copy (one block per row; dead rows are write-only)
// ---------------------------------------------------------------------------
__global__ void __launch_bounds__(256) feat_mask_kernel(
    const float* __restrict__ features, float* __restrict__ out)
{
    const int row = blockIdx.x;
    const int t   = threadIdx.x;
    float4 v = make_float4(0.f, 0.f, 0.f, 0.f);
    if (g_keep[row]) v = ((const float4*)features)[(size_t)row * 256 + t];
    ((float4*)(out + OFF_FEAT))[(size_t)row * 256 + t] = v;
}

// Masked centers + cls_preds (keep floats already written by phase2).
__global__ void __launch_bounds__(256) small_mask_kernel(
    const float* __restrict__ centers, const float* __restrict__ cls_preds,
    float* __restrict__ out)
{
    const int i = blockIdx.x * blockDim.x + threadIdx.x;
    if (i < BB*PP*3) {
        const int pt = i / 3;
        const float m = g_keep[pt] ? 1.f : 0.f;
        out[OFF_CTR + i] = m * centers[i];
        out[OFF_CLS + i] = m * cls_preds[i];
    }
}

extern "C" void kernel_launch(void* const* d_in, const int* in_sizes, int n_in,
                              void* d_out, int out_size)
{
    (void)in_sizes; (void)n_in; (void)out_size;
    const float* centers   = (const float*)d_in[0];
    const float* features  = (const float*)d_in[1];
    const float* cls_preds = (const float*)d_in[2];
    const float* radius    = (const float*)d_in[3];
    float* out = (float*)d_out;

    phase0_sort<<<BB, 1024>>>(centers, cls_preds, radius);
    phase1_matrix<<<BB*KK*10, 256>>>();
    phase2_scan<<<BB*KK, 32>>>(out);
    feat_mask_kernel<<<BB*PP, 256>>>(features, out);
    small_mask_kernel<<<(BB*PP*3 + 255) / 256, 256>>>(centers, cls_preds, out);
}

// round 10
// speedup vs baseline: 9.8350x; 1.0469x over previous
#include <cuda_runtime.h>
#include <stdint.h>

#define BB 8
#define PP 2048
#define CC 1024
#define KK 3
#define NMAX 1024      // per-class capacity (n_k ~ 683 +- 21, >15 sigma safe)
#define WMAX 16        // 64-bit words per matrix row (NMAX/64)

// Output layout (floats): centers*m [B,P,3], features*m [B,P,C], cls*m [B,P,3], keep [B,P]
#define OFF_CTR  0
#define OFF_FEAT (BB*PP*3)
#define OFF_CLS  (OFF_FEAT + BB*PP*CC)
#define OFF_KEEP (OFF_CLS + BB*PP*3)

typedef unsigned long long u64;
typedef unsigned int       u32;

// Scratch (__device__ globals — no allocation)
__device__ float4          g_cpos[BB*KK*NMAX];        // per-class sorted coords
__device__ unsigned short  g_corig[BB*KK*NMAX];       // per-class -> original idx
__device__ int             g_cn[BB*KK];               // per-class counts
__device__ u64             g_cmat[(size_t)BB*KK*NMAX*WMAX];  // 3 MB bitmask
__device__ float           g_T[KK];                   // exact d2 thresholds
__device__ unsigned char   g_keep[BB*PP];

// Upper-triangle 256x256 tiles over NMAX: (rt, ct) with ct >= rt. 10 tiles.
__constant__ unsigned char c_rt[10] = {0,0,0,0, 1,1,1, 2,2, 3};
__constant__ unsigned char c_ct[10] = {0,1,2,3, 1,2,3, 2,3, 3};

// ---------------------------------------------------------------------------
// Phase 0: register-resident bitonic sort. Thread t owns elements 2t, 2t+1.
// Stride j pairs thread t with t^(j>>1): j<=32 -> in-warp shfl (no barrier);
// only j>=64 (15 of 66 stages) touches smem. Key = (label<<44) |
// (~scoremap<<12) | idx, ascending => class-contiguous, score-desc, ties->low
// idx segments. Histogram via ballots; scatter into per-class arrays.
// Block 0 computes exact thresholds T(r) = min{x : __fsqrt_rn(x) >= r}, so
// sqrt_rn(d2) < r <=> d2 < T(r) bit-exactly.
// ---------------------------------------------------------------------------
__global__ void __launch_bounds__(1024) phase0_sort(
    const float* __restrict__ centers,
    const float* __restrict__ cls_preds,
    const float* __restrict__ class_radius)
{
    __shared__ u64 s_key[PP];
    __shared__ int s_cnt[KK];
    __shared__ int s_off[KK];
    const int b = blockIdx.x;
    const int tid = threadIdx.x;
    const float* cp = cls_preds + (size_t)b * PP * KK;
    const float* ct = centers   + (size_t)b * PP * 3;

    if (tid < KK) s_cnt[tid] = 0;
    __syncthreads();

    // Build keys for elements 2t, 2t+1
    u64 v0, v1;
    int lab0, lab1;
    {
        int p = 2*tid;
        float a0 = cp[p*3+0], a1 = cp[p*3+1], a2 = cp[p*3+2];
        float best = a0; lab0 = 0;
        if (a1 > best) { best = a1; lab0 = 1; }
        if (a2 > best) { best = a2; lab0 = 2; }
        u32 u = __float_as_uint(best);
        u = (u & 0x80000000u) ? ~u : (u | 0x80000000u);
        v0 = ((u64)lab0 << 44) | ((u64)(~u) << 12) | (u64)p;
    }
    {
        int p = 2*tid + 1;
        float a0 = cp[p*3+0], a1 = cp[p*3+1], a2 = cp[p*3+2];
        float best = a0; lab1 = 0;
        if (a1 > best) { best = a1; lab1 = 1; }
        if (a2 > best) { best = a2; lab1 = 2; }
        u32 u = __float_as_uint(best);
        u = (u & 0x80000000u) ? ~u : (u | 0x80000000u);
        v1 = ((u64)lab1 << 44) | ((u64)(~u) << 12) | (u64)p;
    }

    // Histogram via ballots (96 shared atomics total instead of 2048)
    #pragma unroll
    for (int c = 0; c < KK; c++) {
        int cnt = __popc(__ballot_sync(0xffffffffu, lab0 == c))
                + __popc(__ballot_sync(0xffffffffu, lab1 == c));
        if ((tid & 31) == 0 && cnt) atomicAdd(&s_cnt[c], cnt);
    }

    // Bitonic sort ascending over 2048 elements.
    for (int k = 2; k <= PP; k <<= 1) {
        const int kh = k >> 1;
        const bool asc = (tid & kh) == 0;     // == ((elem_index & k) == 0)
        for (int j = kh; j >= 1; j >>= 1) {
            if (j >= 64) {
                __syncthreads();              // protect prior reads (WAR)
                s_key[2*tid]   = v0;
                s_key[2*tid+1] = v1;
                __syncthreads();
                int pr = tid ^ (j >> 1);
                u64 u0 = s_key[2*pr], u1 = s_key[2*pr+1];
                bool keepmin = (((tid & (j >> 1)) == 0) == asc);
                v0 = keepmin ? (v0 < u0 ? v0 : u0) : (v0 > u0 ? v0 : u0);
                v1 = keepmin ? (v1 < u1 ? v1 : u1) : (v1 > u1 ? v1 : u1);
            } else if (j >= 2) {
                int d = j >> 1;
                u64 u0 = __shfl_xor_sync(0xffffffffu, v0, d);
                u64 u1 = __shfl_xor_sync(0xffffffffu, v1, d);
                bool keepmin = (((tid & d) == 0) == asc);
                v0 = keepmin ? (v0 < u0 ? v0 : u0) : (v0 > u0 ? v0 : u0);
                v1 = keepmin ? (v1 < u1 ? v1 : u1) : (v1 > u1 ? v1 : u1);
            } else {
                u64 lo = v0 < v1 ? v0 : v1;
                u64 hi = v0 < v1 ? v1 : v0;
                v0 = asc ? lo : hi;
                v1 = asc ? hi : lo;
            }
        }
    }

    __syncthreads();
    if (tid == 0) {
        int o = 0;
        for (int k = 0; k < KK; k++) { s_off[k] = o; o += s_cnt[k]; g_cn[b*KK+k] = s_cnt[k]; }
    }
    __syncthreads();

    // Scatter sorted elements (registers) into per-class arrays.
    #pragma unroll
    for (int q = 0; q < 2; q++) {
        u64 kk  = q ? v1 : v0;
        int pos = 2*tid + q;
        int lab = (int)(kk >> 44);
        int p   = (int)(kk & 0xFFFu);
        int r   = pos - s_off[lab];
        float4 f;
        f.x = ct[p*3+0]; f.y = ct[p*3+1]; f.z = ct[p*3+2]; f.w = 0.f;
        g_cpos [(b*KK+lab)*NMAX + r] = f;
        g_corig[(b*KK+lab)*NMAX + r] = (unsigned short)p;
    }

    if (b == 0 && tid == 0) {
        for (int k = 0; k < KK; k++) {
            float r = class_radius[k];
            float u = 0.f;
            if (r > 0.f) {
                u = __fmul_rn(r, r);
                while (u > 0.f && __fsqrt_rn(u) >= r)
                    u = __uint_as_float(__float_as_uint(u) - 1u);
                while (__fsqrt_rn(u) < r)
                    u = __uint_as_float(__float_as_uint(u) + 1u);
            }
            g_T[k] = u;
        }
    }
}

// ---------------------------------------------------------------------------
// Phase 1: per-class suppression bitmask matrix, upper-triangle 256x256 tiles,
// runtime-clipped to the class size. No label test (class-pure). Rows/cols
// beyond n_k produce garbage bits confined to positions >= n_k (inert).
// ---------------------------------------------------------------------------
__global__ void __launch_bounds__(256) phase1_matrix()
{
    __shared__ float4 cand[256];
    const int bidx = blockIdx.x;
    const int bk = bidx / 10;          // (batch, class) 0..23
    const int t  = bidx % 10;
    const int k  = bk % KK;
    const int n  = g_cn[bk];
    const int nw64 = (n + 63) & ~63;
    const int rowbase  = (int)c_rt[t] * 256;
    const int candbase = (int)c_ct[t] * 256;
    if (rowbase >= n || candbase >= nw64) return;

    const int tid = threadIdx.x;
    const float4* __restrict__ pos = g_cpos + (size_t)bk * NMAX;

    cand[tid] = pos[candbase + tid];
    const float4 me = pos[rowbase + tid];
    const float Ti = g_T[k];
    __syncthreads();

    u64* outp = g_cmat + ((size_t)bk*NMAX + rowbase + tid)*WMAX + (int)c_ct[t]*4;
    #pragma unroll
    for (int wd = 0; wd < 4; wd++) {
        u64 acc = 0;
        #pragma unroll 16
        for (int cc = 0; cc < 64; cc++) {
            float4 f = cand[wd*64 + cc];
            float dx = __fsub_rn(f.x, me.x);
            float dy = __fsub_rn(f.y, me.y);
            float dz = __fsub_rn(f.z, me.z);
            float d2 = __fadd_rn(__fadd_rn(__fmul_rn(dx,dx), __fmul_rn(dy,dy)),
                                 __fmul_rn(dz,dz));
            acc |= ((u64)(d2 < Ti)) << cc;
        }
        outp[wd] = acc;
    }
}

// ---------------------------------------------------------------------------
// Phase 2: one warp per (batch, class) — 24 independent scans. Lane l holds
// running-mask word l; the 64x64 diagonal block of word w is register-local
// to lane w -> pure-ALU serial resolve, no shfl on the chain; one shfl per
// 32 points broadcasts keep bits.
// ---------------------------------------------------------------------------
__global__ void __launch_bounds__(32) phase2_scan(float* __restrict__ out)
{
    const int bk = blockIdx.x;
    const int b  = bk / KK;
    const int n  = g_cn[bk];
    const int nw = (n + 63) >> 6;
    const int lane = threadIdx.x;
    const int ll = lane & 15;
    const u64* __restrict__ rowp = g_cmat + (size_t)bk*NMAX*WMAX;

    u64 ring[64];  // sliding window: ring[j] = word ll of row (window_base + j)
    #pragma unroll
    for (int j = 0; j < 64; j++)
        ring[j] = rowp[(size_t)j*WMAX + ll];

    u64 mask = 0, keepw = 0;

    #pragma unroll 1
    for (int w = 0; w < nw; w++) {
        // ---------------- half A: bits 0..31 of word w ----------------
        {
            u32 av = ~(u32)mask;          // lane w's copy is the live one
            u32 kb = 0;
            #pragma unroll
            for (int j = 0; j < 32; j++) {
                u32 rloUp = (u32)ring[j] & ((j < 31) ? (0xFFFFFFFEu << j) : 0u);
                u32 m = (u32)(((int)(av << (31 - j))) >> 31);  // bcast of alive bit j
                kb |= m & (1u << j);
                av &= ~(m & rloUp);
            }
            kb = __shfl_sync(0xffffffffu, kb, w);
            u64 a0 = 0, a1 = 0, a2 = 0, a3 = 0;
            #pragma unroll
            for (int j = 0; j < 32; j += 4) {
                if (kb & (1u << j))       a0 |= ring[j];
                if (kb & (1u << (j + 1))) a1 |= ring[j + 1];
                if (kb & (1u << (j + 2))) a2 |= ring[j + 2];
                if (kb & (1u << (j + 3))) a3 |= ring[j + 3];
            }
            mask |= (a0 | a1) | (a2 | a3);
            if (lane == w) keepw |= (u64)kb;
            const int base = (2*w + 2) * 32;   // rows for word (w+1), half A
            if (base < NMAX) {
                #pragma unroll
                for (int j = 0; j < 32; j++)
                    ring[j] = rowp[(size_t)(base + j)*WMAX + ll];
            }
        }
        // ---------------- half B: bits 32..63 of word w ----------------
        {
            u32 av = ~(u32)(mask >> 32);
            u32 kb = 0;
            #pragma unroll
            for (int j = 0; j < 32; j++) {
                u32 rhiUp = (u32)(ring[32 + j] >> 32) & ((j < 31) ? (0xFFFFFFFEu << j) : 0u);
                u32 m = (u32)(((int)(av << (31 - j))) >> 31);
                kb |= m & (1u << j);
                av &= ~(m & rhiUp);
            }
            kb = __shfl_sync(0xffffffffu, kb, w);
            u64 a0 = 0, a1 = 0, a2 = 0, a3 = 0;
            #pragma unroll
            for (int j = 0; j < 32; j += 4) {
                if (kb & (1u << j))       a0 |= ring[32 + j];
                if (kb & (1u << (j + 1))) a1 |= ring[32 + j + 1];
                if (kb & (1u << (j + 2))) a2 |= ring[32 + j + 2];
                if (kb & (1u << (j + 3))) a3 |= ring[32 + j + 3];
            }
            mask |= (a0 | a1) | (a2 | a3);
            if (lane == w) keepw |= ((u64)kb) << 32;
            const int base = (2*w + 3) * 32;   // rows for word (w+1), half B
            if (base < NMAX) {
                #pragma unroll
                for (int j = 0; j < 32; j++)
                    ring[32 + j] = rowp[(size_t)(base + j)*WMAX + ll];
            }
        }
    }

    // Epilogue: lane l owns keep bits for class positions [64l, 64l+64)
    const unsigned short* __restrict__ op = g_corig + (size_t)bk*NMAX;
    unsigned char* __restrict__ kp = g_keep + b*PP;
    float* __restrict__ ko = out + OFF_KEEP + b*PP;
    #pragma unroll 8
    for (int bit = 0; bit < 64; bit++) {
        int pos = lane*64 + bit;
        if (pos < n) {
            int ov = op[pos];
            bool kv = (keepw >> bit) & 1ull;
            kp[ov] = kv ? 1 : 0;
            ko[ov] = kv ? 1.f : 0.f;
        }
    }
}

// ---------------------------------------------------------------------------
// Fused output: blocks [0, 16384) do the masked feature copy (one block per
// row; dead rows are write-only); blocks [16384, 16576) do masked centers +
// cls_preds (keep floats already written by phase2).
// ---------------------------------------------------------------------------
__global__ void __launch_bounds__(256) output_kernel(
    const float* __restrict__ features,
    const float* __restrict__ centers,
    const float* __restrict__ cls_preds,
    float* __restrict__ out)
{
    const int blk = blockIdx.x;
    const int t   = threadIdx.x;
    if (blk < BB*PP) {
        float4 v = make_float4(0.f, 0.f, 0.f, 0.f);
        if (g_keep[blk]) v = ((const float4*)features)[(size_t)blk * 256 + t];
        ((float4*)(out + OFF_FEAT))[(size_t)blk * 256 + t] = v;
    } else {
        const int i = (blk - BB*PP) * 256 + t;   // 0 .. BB*PP*3-1 exactly
        const int pt = i / 3;
        const float m = g_keep[pt] ? 1.f : 0.f;
        out[OFF_CTR + i] = m * centers[i];
        out[OFF_CLS + i] = m * cls_preds[i];
    }
}

extern "C" void kernel_launch(void* const* d_in, const int* in_sizes, int n_in,
                              void* d_out, int out_size)
{
    (void)in_sizes; (void)n_in; (void)out_size;
    const float* centers   = (const float*)d_in[0];
    const float* features  = (const float*)d_in[1];
    const float* cls_preds = (const float*)d_in[2];
    const float* radius    = (const float*)d_in[3];
    float* out = (float*)d_out;

    phase0_sort<<<BB, 1024>>>(centers, cls_preds, radius);
    phase1_matrix<<<BB*KK*10, 256>>>();
    phase2_scan<<<BB*KK, 32>>>(out);
    output_kernel<<<BB*PP + (BB*PP*3)/256, 256>>>(features, centers, cls_preds, out);
}

// round 11
// speedup vs baseline: 9.8524x; 1.0018x over previous
#include <cuda_runtime.h>
#include <stdint.h>

#define BB 8
#define PP 2048
#define CC 1024
#define KK 3
#define NP 1024        // per-class capacity (n_k ~ 683 +- 21, >15 sigma safe)

// Output layout (floats): centers*m [B,P,3], features*m [B,P,C], cls*m [B,P,3], keep [B,P]
#define OFF_CTR  0
#define OFF_FEAT (BB*PP*3)
#define OFF_CLS  (OFF_FEAT + BB*PP*CC)
#define OFF_KEEP (OFF_CLS + BB*PP*3)

typedef unsigned long long u64;
typedef unsigned int       u32;

__device__ unsigned char g_keep[BB*PP];

// ---------------------------------------------------------------------------
// Fused NMS: one block per (batch, class). Steps:
//  1. select class members (warp-aggregated append), key = (~scoremap<<12)|idx
//  2. register-resident bitonic sort of 1024 padded keys (asc = score desc,
//     ties -> low idx); pads sort last (key = ~0)
//  3. gather coords (pads = 1e30 -> all pad suppression bits are provably 0)
//  4. per 64-point word w: all 512 threads compute suppression row-words
//     (upper-triangle words l >= w) into smem; warp 0 resolves the diagonal
//     64x64 block with the register-local serial chain (lane l holds mask
//     word l; lane w's smem column is the diagonal), ORs kept rows into the
//     running mask. sqrt replaced exactly: T = min{x : __fsqrt_rn(x) >= r}.
//  5. epilogue scatters keep bits to g_keep + out keep floats.
// ---------------------------------------------------------------------------
__global__ void __launch_bounds__(512) nms_fused(
    const float* __restrict__ centers,
    const float* __restrict__ cls_preds,
    const float* __restrict__ class_radius,
    float* __restrict__ out)
{
    __shared__ u64 s_buf[NP];                  // keys, then srow[64][16]
    __shared__ float s_x[NP], s_y[NP], s_z[NP];
    __shared__ unsigned short s_orig[NP];
    __shared__ int s_n;
    __shared__ float s_T;
    __shared__ u64 s_keep[16];

    const int bk = blockIdx.x;
    const int b = bk / KK;
    const int k = bk % KK;
    const int tid = threadIdx.x;
    const int lane = tid & 31;
    const float* cp = cls_preds + (size_t)b * PP * KK;
    const float* ct = centers   + (size_t)b * PP * 3;

    if (tid == 0) {
        s_n = 0;
        float r = class_radius[k];
        float u = 0.f;
        if (r > 0.f) {
            u = __fmul_rn(r, r);
            while (u > 0.f && __fsqrt_rn(u) >= r)
                u = __uint_as_float(__float_as_uint(u) - 1u);
            while (__fsqrt_rn(u) < r)
                u = __uint_as_float(__float_as_uint(u) + 1u);
        }
        s_T = u;
    }
    __syncthreads();

    // 1. selection (warp-aggregated append; order fixed later by sort)
    #pragma unroll
    for (int q = 0; q < 4; q++) {
        int p = q*512 + tid;
        float a0 = cp[p*3+0], a1 = cp[p*3+1], a2 = cp[p*3+2];
        float best = a0; int lab = 0;
        if (a1 > best) { best = a1; lab = 1; }
        if (a2 > best) { best = a2; lab = 2; }
        u32 ball = __ballot_sync(0xffffffffu, lab == k);
        if (ball) {
            int base = 0;
            if (lane == 0) base = atomicAdd(&s_n, __popc(ball));
            base = __shfl_sync(0xffffffffu, base, 0);
            if (lab == k) {
                u32 u = __float_as_uint(best);
                u = (u & 0x80000000u) ? ~u : (u | 0x80000000u);  // monotone map
                int pos = base + __popc(ball & ((1u << lane) - 1u));
                if (pos < NP) s_buf[pos] = ((u64)(~u) << 12) | (u32)p;
            }
        }
    }
    __syncthreads();
    int n = s_n; if (n > NP) n = NP;
    for (int i = n + tid; i < NP; i += 512) s_buf[i] = ~0ull;
    __syncthreads();

    // 2. register bitonic sort ascending, thread owns elements 2t, 2t+1
    u64 v0 = s_buf[2*tid], v1 = s_buf[2*tid+1];
    for (int kk2 = 2; kk2 <= NP; kk2 <<= 1) {
        const int kh = kk2 >> 1;
        const bool asc = (tid & kh) == 0;
        for (int j = kh; j >= 1; j >>= 1) {
            if (j >= 64) {
                __syncthreads();
                s_buf[2*tid]   = v0;
                s_buf[2*tid+1] = v1;
                __syncthreads();
                int pr = tid ^ (j >> 1);
                u64 u0 = s_buf[2*pr], u1 = s_buf[2*pr+1];
                bool keepmin = (((tid & (j >> 1)) == 0) == asc);
                v0 = keepmin ? (v0 < u0 ? v0 : u0) : (v0 > u0 ? v0 : u0);
                v1 = keepmin ? (v1 < u1 ? v1 : u1) : (v1 > u1 ? v1 : u1);
            } else if (j >= 2) {
                int d = j >> 1;
                u64 u0 = __shfl_xor_sync(0xffffffffu, v0, d);
                u64 u1 = __shfl_xor_sync(0xffffffffu, v1, d);
                bool keepmin = (((tid & d) == 0) == asc);
                v0 = keepmin ? (v0 < u0 ? v0 : u0) : (v0 > u0 ? v0 : u0);
                v1 = keepmin ? (v1 < u1 ? v1 : u1) : (v1 > u1 ? v1 : u1);
            } else {
                u64 lo = v0 < v1 ? v0 : v1;
                u64 hi = v0 < v1 ? v1 : v0;
                v0 = asc ? lo : hi;
                v1 = asc ? hi : lo;
            }
        }
    }
    __syncthreads();
    s_buf[2*tid] = v0; s_buf[2*tid+1] = v1;
    __syncthreads();

    // 3. gather coords; pads -> 1e30 (=> inf distances => zero bits)
    for (int s = tid; s < NP; s += 512) {
        if (s < n) {
            int p = (int)(s_buf[s] & 0xFFFu);
            s_orig[s] = (unsigned short)p;
            s_x[s] = ct[p*3+0]; s_y[s] = ct[p*3+1]; s_z[s] = ct[p*3+2];
        } else {
            s_x[s] = 1e30f; s_y[s] = 1e30f; s_z[s] = 1e30f;
        }
    }

    // 4. NMS word steps
    u64* s_row = s_buf;                 // reuse: s_row[j*16 + l]
    const float Ti = s_T;
    const int nw = (n + 63) >> 6;
    const int ll = lane & 15;
    u64 mask = 0;

    #pragma unroll 1
    for (int w = 0; w < nw; w++) {
        __syncthreads();                // srow reuse + first-iter coord fence
        {
            const int j  = tid & 63;
            const int c8 = tid >> 6;    // 0..7
            const int rowg = w*64 + j;
            const float xr = s_x[rowg], yr = s_y[rowg], zr = s_z[rowg];
            for (int l = w + c8; l < nw; l += 8) {
                u64 acc = 0;
                const int cb = l*64;
                #pragma unroll 16
                for (int cc = 0; cc < 64; cc++) {
                    float dx = __fsub_rn(s_x[cb+cc], xr);
                    float dy = __fsub_rn(s_y[cb+cc], yr);
                    float dz = __fsub_rn(s_z[cb+cc], zr);
                    float d2 = __fadd_rn(__fadd_rn(__fmul_rn(dx,dx), __fmul_rn(dy,dy)),
                                         __fmul_rn(dz,dz));
                    acc |= ((u64)(d2 < Ti)) << cc;
                }
                s_row[j*16 + l] = acc;
            }
        }
        __syncthreads();
        if (tid < 32) {
            // half A: bits 0..31 of word w (rows 64w .. 64w+31)
            u32 av = ~(u32)mask;        // lane w's copy is the live one
            u32 kbA = 0;
            #pragma unroll 8
            for (int j = 0; j < 32; j++) {
                u32 rloUp = (u32)s_row[j*16 + ll] & ((j < 31) ? (0xFFFFFFFEu << j) : 0u);
                u32 m = (u32)(((int)(av << (31 - j))) >> 31);
                kbA |= m & (1u << j);
                av &= ~(m & rloUp);
            }
            kbA = __shfl_sync(0xffffffffu, kbA, w);   // w <= 15 == ll on lane w
            {
                u64 a0 = 0, a1 = 0;
                #pragma unroll 8
                for (int j = 0; j < 32; j += 2) {
                    if (kbA & (1u << j))     a0 |= s_row[j*16 + ll];
                    if (kbA & (1u << (j+1))) a1 |= s_row[(j+1)*16 + ll];
                }
                mask |= a0 | a1;
            }
            // half B: bits 32..63 of word w (rows 64w+32 .. 64w+63)
            u32 av2 = ~(u32)(mask >> 32);
            u32 kbB = 0;
            #pragma unroll 8
            for (int j = 0; j < 32; j++) {
                u32 rhiUp = (u32)(s_row[(32+j)*16 + ll] >> 32) & ((j < 31) ? (0xFFFFFFFEu << j) : 0u);
                u32 m = (u32)(((int)(av2 << (31 - j))) >> 31);
                kbB |= m & (1u << j);
                av2 &= ~(m & rhiUp);
            }
            kbB = __shfl_sync(0xffffffffu, kbB, w);
            {
                u64 a0 = 0, a1 = 0;
                #pragma unroll 8
                for (int j = 0; j < 32; j += 2) {
                    if (kbB & (1u << j))     a0 |= s_row[(32+j)*16 + ll];
                    if (kbB & (1u << (j+1))) a1 |= s_row[(33+j)*16 + ll];
                }
                mask |= a0 | a1;
            }
            if (lane == w) s_keep[w] = (u64)kbA | ((u64)kbB << 32);
        }
    }
    __syncthreads();

    // 5. epilogue
    unsigned char* kp = g_keep + b*PP;
    float* ko = out + OFF_KEEP + b*PP;
    for (int pos = tid; pos < n; pos += 512) {
        bool kv = (s_keep[pos >> 6] >> (pos & 63)) & 1ull;
        int ov = s_orig[pos];
        kp[ov] = kv ? 1 : 0;
        ko[ov] = kv ? 1.f : 0.f;
    }
}

// ---------------------------------------------------------------------------
// Output: blocks [0,2048): 8 independent float4s per thread (MLP=8) for the
// masked feature copy (dead rows write-only). Blocks [2048,2240): masked
// centers + cls_preds. Keep floats already written by nms_fused.
// ---------------------------------------------------------------------------
__global__ void __launch_bounds__(256) output_kernel(
    const float* __restrict__ features,
    const float* __restrict__ centers,
    const float* __restrict__ cls_preds,
    float* __restrict__ out)
{
    const int blk = blockIdx.x;
    const int t   = threadIdx.x;
    if (blk < 2048) {
        const float4* __restrict__ f4 = (const float4*)features;
        float4* __restrict__ o4 = (float4*)(out + OFF_FEAT);
        #pragma unroll
        for (int q = 0; q < 8; q++) {
            int i = blk*2048 + q*256 + t;       // covers BB*PP*CC/4 = 4,194,304
            int row = i >> 8;                   // 256 float4 per row
            float4 v = make_float4(0.f, 0.f, 0.f, 0.f);
            if (g_keep[row]) v = f4[i];
            o4[i] = v;
        }
    } else {
        const int i = (blk - 2048) * 256 + t;   // 0 .. BB*PP*3-1 exactly
        const int pt = i / 3;
        const float m = g_keep[pt] ? 1.f : 0.f;
        out[OFF_CTR + i] = m * centers[i];
        out[OFF_CLS + i] = m * cls_preds[i];
    }
}

extern "C" void kernel_launch(void* const* d_in, const int* in_sizes, int n_in,
                              void* d_out, int out_size)
{
    (void)in_sizes; (void)n_in; (void)out_size;
    const float* centers   = (const float*)d_in[0];
    const float* features  = (const float*)d_in[1];
    const float* cls_preds = (const float*)d_in[2];
    const float* radius    = (const float*)d_in[3];
    float* out = (float*)d_out;

    nms_fused<<<BB*KK, 512>>>(centers, cls_preds, radius, out);
    output_kernel<<<2048 + (BB*PP*3)/256, 256>>>(features, centers, cls_preds, out);
}

// round 12
// speedup vs baseline: 12.2395x; 1.2423x over previous
#include <cuda_runtime.h>
#include <stdint.h>

#define BB 8
#define PP 2048
#define CC 1024
#define KK 3
#define NP 1024        // per-class capacity (n_k ~ 683 +- 21, >15 sigma safe)
#define WMAX 16        // u64 words per matrix row (NP/64)

// Output layout (floats): centers*m [B,P,3], features*m [B,P,C], cls*m [B,P,3], keep [B,P]
#define OFF_CTR  0
#define OFF_FEAT (BB*PP*3)
#define OFF_CLS  (OFF_FEAT + BB*PP*CC)
#define OFF_KEEP (OFF_CLS + BB*PP*3)

typedef unsigned long long u64;
typedef unsigned int       u32;

// Scratch (__device__ globals — no allocation)
__device__ float4          g_cpos[BB*KK*NP];          // per-class sorted coords (pads 1e30)
__device__ unsigned short  g_corig[BB*KK*NP];         // per-class -> original idx
__device__ int             g_cn[BB*KK];               // per-class counts
__device__ u64             g_cmat[(size_t)BB*KK*NP*WMAX];  // 3 MB bitmask (L2-resident)
__device__ float           g_T[KK];                   // exact d2 thresholds
__device__ unsigned char   g_keep[BB*PP];

// Upper-triangle 256x256 tiles over NP: (rt, ct) with ct >= rt. 10 tiles.
__constant__ unsigned char c_rt[10] = {0,0,0,0, 1,1,1, 2,2, 3};
__constant__ unsigned char c_ct[10] = {0,1,2,3, 1,2,3, 2,3, 3};

// ---------------------------------------------------------------------------
// A1: one block per (batch, class): warp-aggregated class selection,
// register-resident bitonic sort (key = (~scoremap<<12)|idx, asc => score
// desc, ties -> low idx; pads sort last), gather coords (pads = 1e30 so all
// pad suppression bits vs real points are provably zero). Also computes the
// exact sqrt threshold T = min{x : __fsqrt_rn(x) >= r} (sqrt_rn(d2) < r
// <=> d2 < T, bit-exact).
// ---------------------------------------------------------------------------
__global__ void __launch_bounds__(512) phase_a1(
    const float* __restrict__ centers,
    const float* __restrict__ cls_preds,
    const float* __restrict__ class_radius)
{
    __shared__ u64 s_buf[NP];
    __shared__ int s_n;

    const int bk = blockIdx.x;
    const int b = bk / KK;
    const int k = bk % KK;
    const int tid = threadIdx.x;
    const int lane = tid & 31;
    const float* cp = cls_preds + (size_t)b * PP * KK;
    const float* ct = centers   + (size_t)b * PP * 3;

    if (tid == 0) {
        s_n = 0;
        float r = class_radius[k];
        float u = 0.f;
        if (r > 0.f) {
            u = __fmul_rn(r, r);
            while (u > 0.f && __fsqrt_rn(u) >= r)
                u = __uint_as_float(__float_as_uint(u) - 1u);
            while (__fsqrt_rn(u) < r)
                u = __uint_as_float(__float_as_uint(u) + 1u);
        }
        g_T[k] = u;           // all b blocks of class k write the same value
    }
    __syncthreads();

    // selection (warp-aggregated append; order fixed by the sort)
    #pragma unroll
    for (int q = 0; q < 4; q++) {
        int p = q*512 + tid;
        float a0 = cp[p*3+0], a1 = cp[p*3+1], a2 = cp[p*3+2];
        float best = a0; int lab = 0;
        if (a1 > best) { best = a1; lab = 1; }
        if (a2 > best) { best = a2; lab = 2; }
        u32 ball = __ballot_sync(0xffffffffu, lab == k);
        if (ball) {
            int base = 0;
            if (lane == 0) base = atomicAdd(&s_n, __popc(ball));
            base = __shfl_sync(0xffffffffu, base, 0);
            if (lab == k) {
                u32 u = __float_as_uint(best);
                u = (u & 0x80000000u) ? ~u : (u | 0x80000000u);  // monotone map
                int pos = base + __popc(ball & ((1u << lane) - 1u));
                if (pos < NP) s_buf[pos] = ((u64)(~u) << 12) | (u32)p;
            }
        }
    }
    __syncthreads();
    int n = s_n; if (n > NP) n = NP;
    for (int i = n + tid; i < NP; i += 512) s_buf[i] = ~0ull;
    __syncthreads();

    // register bitonic sort ascending; thread owns elements 2t, 2t+1
    u64 v0 = s_buf[2*tid], v1 = s_buf[2*tid+1];
    for (int kk2 = 2; kk2 <= NP; kk2 <<= 1) {
        const int kh = kk2 >> 1;
        const bool asc = (tid & kh) == 0;
        for (int j = kh; j >= 1; j >>= 1) {
            if (j >= 64) {
                __syncthreads();
                s_buf[2*tid]   = v0;
                s_buf[2*tid+1] = v1;
                __syncthreads();
                int pr = tid ^ (j >> 1);
                u64 u0 = s_buf[2*pr], u1 = s_buf[2*pr+1];
                bool keepmin = (((tid & (j >> 1)) == 0) == asc);
                v0 = keepmin ? (v0 < u0 ? v0 : u0) : (v0 > u0 ? v0 : u0);
                v1 = keepmin ? (v1 < u1 ? v1 : u1) : (v1 > u1 ? v1 : u1);
            } else if (j >= 2) {
                int d = j >> 1;
                u64 u0 = __shfl_xor_sync(0xffffffffu, v0, d);
                u64 u1 = __shfl_xor_sync(0xffffffffu, v1, d);
                bool keepmin = (((tid & d) == 0) == asc);
                v0 = keepmin ? (v0 < u0 ? v0 : u0) : (v0 > u0 ? v0 : u0);
                v1 = keepmin ? (v1 < u1 ? v1 : u1) : (v1 > u1 ? v1 : u1);
            } else {
                u64 lo = v0 < v1 ? v0 : v1;
                u64 hi = v0 < v1 ? v1 : v0;
                v0 = asc ? lo : hi;
                v1 = asc ? hi : lo;
            }
        }
    }

    // scatter sorted elements to globals (pads -> 1e30)
    if (tid == 0) g_cn[bk] = n;
    #pragma unroll
    for (int q = 0; q < 2; q++) {
        u64 kk  = q ? v1 : v0;
        int pos = 2*tid + q;
        float4 f;
        if (pos < n) {
            int p = (int)(kk & 0xFFFu);
            g_corig[(size_t)bk*NP + pos] = (unsigned short)p;
            f.x = ct[p*3+0]; f.y = ct[p*3+1]; f.z = ct[p*3+2]; f.w = 0.f;
        } else {
            f.x = 1e30f; f.y = 1e30f; f.z = 1e30f; f.w = 0.f;
        }
        g_cpos[(size_t)bk*NP + pos] = f;
    }
}

// ---------------------------------------------------------------------------
// A2: chip-wide per-class suppression matrix, upper-triangle 256x256 tiles,
// runtime-clipped. Garbage/stale words are confined to positions >= n or
// lower-triangle words (consumed before they can be polluted) — inert.
// ---------------------------------------------------------------------------
__global__ void __launch_bounds__(256) phase_a2()
{
    __shared__ float4 cand[256];
    const int bidx = blockIdx.x;
    const int bk = bidx / 10;          // (batch, class) 0..23
    const int t  = bidx % 10;
    const int k  = bk % KK;
    const int n  = g_cn[bk];
    const int nw64 = (n + 63) & ~63;
    const int rowbase  = (int)c_rt[t] * 256;
    const int candbase = (int)c_ct[t] * 256;
    if (rowbase >= n || candbase >= nw64) return;

    const int tid = threadIdx.x;
    const float4* __restrict__ pos = g_cpos + (size_t)bk * NP;

    cand[tid] = pos[candbase + tid];
    const float4 me = pos[rowbase + tid];
    const float Ti = g_T[k];
    __syncthreads();

    u64* outp = g_cmat + ((size_t)bk*NP + rowbase + tid)*WMAX + (int)c_ct[t]*4;
    #pragma unroll
    for (int wd = 0; wd < 4; wd++) {
        u64 acc = 0;
        #pragma unroll 16
        for (int cc = 0; cc < 64; cc++) {
            float4 f = cand[wd*64 + cc];
            float dx = __fsub_rn(f.x, me.x);
            float dy = __fsub_rn(f.y, me.y);
            float dz = __fsub_rn(f.z, me.z);
            float d2 = __fadd_rn(__fadd_rn(__fmul_rn(dx,dx), __fmul_rn(dy,dy)),
                                 __fmul_rn(dz,dz));
            acc |= ((u64)(d2 < Ti)) << cc;
        }
        outp[wd] = acc;
    }
}

// ---------------------------------------------------------------------------
// A3: resolve, one block per (batch, class). Ring lives in SMEM (no register
// spills), double-buffered: warps 1..15 copy the next 64-row x 16-word block
// (8 KB, contiguous) from L2 while warp 0 runs the diagonal register-local
// serial chain on the current block (loads off-chain, ~12 cyc/bit).
// ---------------------------------------------------------------------------
__global__ void __launch_bounds__(512) phase_a3(float* __restrict__ out)
{
    __shared__ u64 buf[2][64*WMAX];    // 16 KB
    __shared__ u64 s_keep[WMAX];

    const int bk = blockIdx.x;
    const int b  = bk / KK;
    const int n  = g_cn[bk];
    const int nw = (n + 63) >> 6;
    const int tid = threadIdx.x;
    const int lane = tid & 31;
    const u64* __restrict__ rowp = g_cmat + (size_t)bk*NP*WMAX;

    for (int i = tid; i < 64*WMAX; i += 512) buf[0][i] = rowp[i];
    __syncthreads();

    u64 mask = 0;                      // meaningful in warp 0 only
    #pragma unroll 1
    for (int w = 0; w < nw; w++) {
        if (tid >= 32) {
            if (w + 1 < nw) {          // prefetch next word-block
                const u64* src = rowp + (size_t)(w + 1) * 64 * WMAX;
                u64* dst = buf[(w + 1) & 1];
                for (int i = tid - 32; i < 64*WMAX; i += 480) dst[i] = src[i];
            }
        } else {
            const u64* sr = buf[w & 1];
            const int ll = lane & 15;
            // half A: bits 0..31 of word w (rows 64w .. 64w+31)
            u32 av = ~(u32)mask;       // lane w's copy is the live one
            u32 kbA = 0;
            #pragma unroll 8
            for (int j = 0; j < 32; j++) {
                u32 rloUp = (u32)sr[j*WMAX + ll] & ((j < 31) ? (0xFFFFFFFEu << j) : 0u);
                u32 m = (u32)(((int)(av << (31 - j))) >> 31);
                kbA |= m & (1u << j);
                av &= ~(m & rloUp);
            }
            kbA = __shfl_sync(0xffffffffu, kbA, w);
            {
                u64 a0 = 0, a1 = 0;
                #pragma unroll 8
                for (int j = 0; j < 32; j += 2) {
                    if (kbA & (1u << j))     a0 |= sr[j*WMAX + ll];
                    if (kbA & (1u << (j+1))) a1 |= sr[(j+1)*WMAX + ll];
                }
                mask |= a0 | a1;
            }
            // half B: bits 32..63 of word w (rows 64w+32 .. 64w+63)
            u32 av2 = ~(u32)(mask >> 32);
            u32 kbB = 0;
            #pragma unroll 8
            for (int j = 0; j < 32; j++) {
                u32 rhiUp = (u32)(sr[(32+j)*WMAX + ll] >> 32) & ((j < 31) ? (0xFFFFFFFEu << j) : 0u);
                u32 m = (u32)(((int)(av2 << (31 - j))) >> 31);
                kbB |= m & (1u << j);
                av2 &= ~(m & rhiUp);
            }
            kbB = __shfl_sync(0xffffffffu, kbB, w);
            {
                u64 a0 = 0, a1 = 0;
                #pragma unroll 8
                for (int j = 0; j < 32; j += 2) {
                    if (kbB & (1u << j))     a0 |= sr[(32+j)*WMAX + ll];
                    if (kbB & (1u << (j+1))) a1 |= sr[(33+j)*WMAX + ll];
                }
                mask |= a0 | a1;
            }
            if (lane == w) s_keep[w] = (u64)kbA | ((u64)kbB << 32);
        }
        __syncthreads();
    }

    // epilogue: scatter keep bits (g_keep bytes + out keep floats)
    const unsigned short* __restrict__ op = g_corig + (size_t)bk*NP;
    unsigned char* kp = g_keep + b*PP;
    float* ko = out + OFF_KEEP + b*PP;
    for (int pos = tid; pos < n; pos += 512) {
        bool kv = (s_keep[pos >> 6] >> (pos & 63)) & 1ull;
        int ov = op[pos];
        kp[ov] = kv ? 1 : 0;
        ko[ov] = kv ? 1.f : 0.f;
    }
}

// ---------------------------------------------------------------------------
// Output: blocks [0,2048): 8 independent float4s per thread (MLP=8) for the
// masked feature copy (dead rows write-only). Blocks [2048,2240): masked
// centers + cls_preds. Keep floats already written by phase_a3.
// ---------------------------------------------------------------------------
__global__ void __launch_bounds__(256) output_kernel(
    const float* __restrict__ features,
    const float* __restrict__ centers,
    const float* __restrict__ cls_preds,
    float* __restrict__ out)
{
    const int blk = blockIdx.x;
    const int t   = threadIdx.x;
    if (blk < 2048) {
        const float4* __restrict__ f4 = (const float4*)features;
        float4* __restrict__ o4 = (float4*)(out + OFF_FEAT);
        #pragma unroll
        for (int q = 0; q < 8; q++) {
            int i = blk*2048 + q*256 + t;       // covers BB*PP*CC/4 = 4,194,304
            int row = i >> 8;                   // 256 float4 per row
            float4 v = make_float4(0.f, 0.f, 0.f, 0.f);
            if (g_keep[row]) v = f4[i];
            o4[i] = v;
        }
    } else {
        const int i = (blk - 2048) * 256 + t;   // 0 .. BB*PP*3-1 exactly
        const int pt = i / 3;
        const float m = g_keep[pt] ? 1.f : 0.f;
        out[OFF_CTR + i] = m * centers[i];
        out[OFF_CLS + i] = m * cls_preds[i];
    }
}

extern "C" void kernel_launch(void* const* d_in, const int* in_sizes, int n_in,
                              void* d_out, int out_size)
{
    (void)in_sizes; (void)n_in; (void)out_size;
    const float* centers   = (const float*)d_in[0];
    const float* features  = (const float*)d_in[1];
    const float* cls_preds = (const float*)d_in[2];
    const float* radius    = (const float*)d_in[3];
    float* out = (float*)d_out;

    phase_a1<<<BB*KK, 512>>>(centers, cls_preds, radius);
    phase_a2<<<BB*KK*10, 256>>>();
    phase_a3<<<BB*KK, 512>>>(out);
    output_kernel<<<2048 + (BB*PP*3)/256, 256>>>(features, centers, cls_preds, out);
}

// round 13
// speedup vs baseline: 12.7448x; 1.0413x over previous
#include <cuda_runtime.h>
#include <stdint.h>

#define BB 8
#define PP 2048
#define CC 1024
#define KK 3
#define NP 1024        // per-class capacity (n_k ~ 683 +- 21, >15 sigma safe)
#define WMAX 16        // u64 words per matrix row (NP/64)
#define NBK (BB*KK)    // 24 (batch, class) pairs
#define NTILE 10       // upper-triangle 256x256 tiles per (batch, class)

// Output layout (floats): centers*m [B,P,3], features*m [B,P,C], cls*m [B,P,3], keep [B,P]
#define OFF_CTR  0
#define OFF_FEAT (BB*PP*3)
#define OFF_CLS  (OFF_FEAT + BB*PP*CC)
#define OFF_KEEP (OFF_CLS + BB*PP*3)

typedef unsigned long long u64;
typedef unsigned int       u32;

// Scratch (__device__ globals — no allocation)
__device__ float4          g_cpos[NBK*NP];            // per-class sorted coords (pads 1e30)
__device__ unsigned short  g_corig[NBK*NP];           // per-class -> original idx
__device__ u64             g_cmat[(size_t)NBK*NP*WMAX];  // 3 MB bitmask (L2-resident)
__device__ float           g_T[KK];                   // exact d2 thresholds
__device__ unsigned char   g_keep[BB*PP];
__device__ int             g_flag[NBK];               // A1-done flags (reset in-kernel)
__device__ int             g_done[NBK];               // tile counters  (reset in-kernel)
__device__ int             g_n[NBK];                  // class sizes

// Upper-triangle tiles: (rt, ct) with ct >= rt.
__constant__ unsigned char c_rt[NTILE] = {0,0,0,0, 1,1,1, 2,2, 3};
__constant__ unsigned char c_ct[NTILE] = {0,1,2,3, 1,2,3, 2,3, 3};

// ---------------------------------------------------------------------------
// Single fused NMS kernel. 264 blocks x 512 threads, all co-resident in
// wave 1 (<= 4 CTAs/SM x 148 SMs), so intra-grid spin sync is deadlock-free.
//
// Blocks 0..23 (bk = bid):
//   A1: warp-aggregated class selection; register bitonic sort of 1024 padded
//       keys (key = (~scoremap<<12)|idx, asc => score desc, ties -> low idx;
//       pads sort last); gather coords (pads = 1e30 => pad suppression bits
//       vs real points provably 0). Exact threshold T = min{x: sqrt_rn(x)>=r}
//       so sqrt_rn(d2) < r <=> d2 < T bit-exactly.
//   release flag -> wait 10 tiles -> A3 resolve (smem double-buffered ring;
//   warp 0 runs the diagonal register-local serial chain, warps 1..15
//   prefetch the next 8 KB word-block) -> epilogue -> reset flags.
//
// Blocks 24..263: wait flag -> one 256x256 upper-tri matrix tile (2 u64
//   words per thread) -> fence -> count done.
// ---------------------------------------------------------------------------
__global__ void __launch_bounds__(512) nms_all(
    const float* __restrict__ centers,
    const float* __restrict__ cls_preds,
    const float* __restrict__ class_radius,
    float* __restrict__ out)
{
    __shared__ u64 sh[2*64*WMAX + WMAX];   // 16.6 KB, overlaid per phase
    __shared__ int s_n;

    const int bid = blockIdx.x;
    const int tid = threadIdx.x;
    const int lane = tid & 31;

    if (bid >= NBK) {
        // ------------------- matrix tile block -------------------
        const int idx = bid - NBK;
        const int bk  = idx / NTILE;
        const int t   = idx % NTILE;
        const int k   = bk % KK;

        if (tid == 0) { while (atomicAdd(&g_flag[bk], 0) == 0) __nanosleep(100); }
        __syncthreads();
        __threadfence();

        const int n = g_n[bk];
        const int nw64 = (n + 63) & ~63;
        const int rowbase  = (int)c_rt[t] * 256;
        const int candbase = (int)c_ct[t] * 256;

        if (rowbase < n && candbase < nw64) {
            float4* cand = (float4*)sh;          // 256 float4 = 4 KB
            const float4* __restrict__ pos = g_cpos + (size_t)bk * NP;
            if (tid < 256) cand[tid] = pos[candbase + tid];
            const int r    = tid & 255;
            const int half = tid >> 8;           // 0 or 1 -> words {0,1} or {2,3}
            const float4 me = pos[rowbase + r];
            const float Ti = g_T[k];
            __syncthreads();

            u64* outp = g_cmat + ((size_t)bk*NP + rowbase + r)*WMAX + (int)c_ct[t]*4 + half*2;
            #pragma unroll
            for (int wd = 0; wd < 2; wd++) {
                u64 acc = 0;
                const int cb = half*128 + wd*64;
                #pragma unroll 16
                for (int cc = 0; cc < 64; cc++) {
                    float4 f = cand[cb + cc];
                    float dx = __fsub_rn(f.x, me.x);
                    float dy = __fsub_rn(f.y, me.y);
                    float dz = __fsub_rn(f.z, me.z);
                    float d2 = __fadd_rn(__fadd_rn(__fmul_rn(dx,dx), __fmul_rn(dy,dy)),
                                         __fmul_rn(dz,dz));
                    acc |= ((u64)(d2 < Ti)) << cc;
                }
                outp[wd] = acc;
            }
        }
        __threadfence();
        __syncthreads();
        if (tid == 0) atomicAdd(&g_done[bk], 1);
        return;
    }

    // ------------------------- A1 + A3 block -------------------------
    const int bk = bid;
    const int b = bk / KK;
    const int k = bk % KK;
    const float* cp = cls_preds + (size_t)b * PP * KK;
    const float* ct = centers   + (size_t)b * PP * 3;
    u64* s_buf = sh;                       // first 1024 u64 for A1

    if (tid == 0) {
        s_n = 0;
        float r = class_radius[k];
        float u = 0.f;
        if (r > 0.f) {
            u = __fmul_rn(r, r);
            while (u > 0.f && __fsqrt_rn(u) >= r)
                u = __uint_as_float(__float_as_uint(u) - 1u);
            while (__fsqrt_rn(u) < r)
                u = __uint_as_float(__float_as_uint(u) + 1u);
        }
        g_T[k] = u;                        // all b-blocks of class k write same value
    }
    __syncthreads();

    // A1 selection (warp-aggregated append; order fixed by sort — keys unique)
    #pragma unroll
    for (int q = 0; q < 4; q++) {
        int p = q*512 + tid;
        float a0 = cp[p*3+0], a1 = cp[p*3+1], a2 = cp[p*3+2];
        float best = a0; int lab = 0;
        if (a1 > best) { best = a1; lab = 1; }
        if (a2 > best) { best = a2; lab = 2; }
        u32 ball = __ballot_sync(0xffffffffu, lab == k);
        if (ball) {
            int base = 0;
            if (lane == 0) base = atomicAdd(&s_n, __popc(ball));
            base = __shfl_sync(0xffffffffu, base, 0);
            if (lab == k) {
                u32 u = __float_as_uint(best);
                u = (u & 0x80000000u) ? ~u : (u | 0x80000000u);  // monotone map
                int pos = base + __popc(ball & ((1u << lane) - 1u));
                if (pos < NP) s_buf[pos] = ((u64)(~u) << 12) | (u32)p;
            }
        }
    }
    __syncthreads();
    int n = s_n; if (n > NP) n = NP;
    for (int i = n + tid; i < NP; i += 512) s_buf[i] = ~0ull;
    __syncthreads();

    // A1 register bitonic sort ascending; thread owns elements 2t, 2t+1
    u64 v0 = s_buf[2*tid], v1 = s_buf[2*tid+1];
    for (int kk2 = 2; kk2 <= NP; kk2 <<= 1) {
        const int kh = kk2 >> 1;
        const bool asc = (tid & kh) == 0;
        for (int j = kh; j >= 1; j >>= 1) {
            if (j >= 64) {
                __syncthreads();
                s_buf[2*tid]   = v0;
                s_buf[2*tid+1] = v1;
                __syncthreads();
                int pr = tid ^ (j >> 1);
                u64 u0 = s_buf[2*pr], u1 = s_buf[2*pr+1];
                bool keepmin = (((tid & (j >> 1)) == 0) == asc);
                v0 = keepmin ? (v0 < u0 ? v0 : u0) : (v0 > u0 ? v0 : u0);
                v1 = keepmin ? (v1 < u1 ? v1 : u1) : (v1 > u1 ? v1 : u1);
            } else if (j >= 2) {
                int d = j >> 1;
                u64 u0 = __shfl_xor_sync(0xffffffffu, v0, d);
                u64 u1 = __shfl_xor_sync(0xffffffffu, v1, d);
                bool keepmin = (((tid & d) == 0) == asc);
                v0 = keepmin ? (v0 < u0 ? v0 : u0) : (v0 > u0 ? v0 : u0);
                v1 = keepmin ? (v1 < u1 ? v1 : u1) : (v1 > u1 ? v1 : u1);
            } else {
                u64 lo = v0 < v1 ? v0 : v1;
                u64 hi = v0 < v1 ? v1 : v0;
                v0 = asc ? lo : hi;
                v1 = asc ? hi : lo;
            }
        }
    }

    // A1 scatter (pads -> 1e30)
    if (tid == 0) g_n[bk] = n;
    #pragma unroll
    for (int q = 0; q < 2; q++) {
        u64 kk  = q ? v1 : v0;
        int pos = 2*tid + q;
        float4 f;
        if (pos < n) {
            int p = (int)(kk & 0xFFFu);
            g_corig[(size_t)bk*NP + pos] = (unsigned short)p;
            f.x = ct[p*3+0]; f.y = ct[p*3+1]; f.z = ct[p*3+2]; f.w = 0.f;
        } else {
            f.x = 1e30f; f.y = 1e30f; f.z = 1e30f; f.w = 0.f;
        }
        g_cpos[(size_t)bk*NP + pos] = f;
    }

    // release to tile blocks
    __threadfence();
    __syncthreads();
    if (tid == 0) atomicExch(&g_flag[bk], 1);

    // wait for the 10 tiles
    if (tid == 0) { while (atomicAdd(&g_done[bk], 0) < NTILE) __nanosleep(100); }
    __syncthreads();
    __threadfence();

    // ---------------- A3 resolve ----------------
    u64* buf0 = sh;
    u64* buf1 = sh + 64*WMAX;
    u64* s_keep = sh + 2*64*WMAX;
    const int nw = (n + 63) >> 6;
    const u64* __restrict__ rowp = g_cmat + (size_t)bk*NP*WMAX;

    for (int i = tid; i < 64*WMAX; i += 512) buf0[i] = rowp[i];
    __syncthreads();

    u64 mask = 0;                          // meaningful in warp 0 only
    #pragma unroll 1
    for (int w = 0; w < nw; w++) {
        if (tid >= 32) {
            if (w + 1 < nw) {              // prefetch next word-block
                const u64* src = rowp + (size_t)(w + 1) * 64 * WMAX;
                u64* dst = (w & 1) ? buf0 : buf1;
                for (int i = tid - 32; i < 64*WMAX; i += 480) dst[i] = src[i];
            }
        } else {
            const u64* sr = (w & 1) ? buf1 : buf0;
            const int ll = lane & 15;
            // half A: bits 0..31 of word w (rows 64w .. 64w+31)
            u32 av = ~(u32)mask;           // lane w's copy is the live one
            u32 kbA = 0;
            #pragma unroll 8
            for (int j = 0; j < 32; j++) {
                u32 rloUp = (u32)sr[j*WMAX + ll] & ((j < 31) ? (0xFFFFFFFEu << j) : 0u);
                u32 m = (u32)(((int)(av << (31 - j))) >> 31);
                kbA |= m & (1u << j);
                av &= ~(m & rloUp);
            }
            kbA = __shfl_sync(0xffffffffu, kbA, w);
            {
                u64 a0 = 0, a1 = 0;
                #pragma unroll 8
                for (int j = 0; j < 32; j += 2) {
                    if (kbA & (1u << j))     a0 |= sr[j*WMAX + ll];
                    if (kbA & (1u << (j+1))) a1 |= sr[(j+1)*WMAX + ll];
                }
                mask |= a0 | a1;
            }
            // half B: bits 32..63 of word w (rows 64w+32 .. 64w+63)
            u32 av2 = ~(u32)(mask >> 32);
            u32 kbB = 0;
            #pragma unroll 8
            for (int j = 0; j < 32; j++) {
                u32 rhiUp = (u32)(sr[(32+j)*WMAX + ll] >> 32) & ((j < 31) ? (0xFFFFFFFEu << j) : 0u);
                u32 m = (u32)(((int)(av2 << (31 - j))) >> 31);
                kbB |= m & (1u << j);
                av2 &= ~(m & rhiUp);
            }
            kbB = __shfl_sync(0xffffffffu, kbB, w);
            {
                u64 a0 = 0, a1 = 0;
                #pragma unroll 8
                for (int j = 0; j < 32; j += 2) {
                    if (kbB & (1u << j))     a0 |= sr[(32+j)*WMAX + ll];
                    if (kbB & (1u << (j+1))) a1 |= sr[(33+j)*WMAX + ll];
                }
                mask |= a0 | a1;
            }
            if (lane == w) s_keep[w] = (u64)kbA | ((u64)kbB << 32);
        }
        __syncthreads();
    }

    // epilogue: scatter keep bits (g_keep bytes + out keep floats)
    const unsigned short* __restrict__ op = g_corig + (size_t)bk*NP;
    unsigned char* kp = g_keep + b*PP;
    float* ko = out + OFF_KEEP + b*PP;
    for (int pos = tid; pos < n; pos += 512) {
        bool kv = (s_keep[pos >> 6] >> (pos & 63)) & 1ull;
        int ov = op[pos];
        kp[ov] = kv ? 1 : 0;
        ko[ov] = kv ? 1.f : 0.f;
    }

    // reset flags for the next graph replay (race-free: done==10 means all
    // tile blocks have finished touching flag/done for this bk)
    __syncthreads();
    if (tid == 0) { atomicExch(&g_flag[bk], 0); atomicExch(&g_done[bk], 0); }
}

// ---------------------------------------------------------------------------
// Output: blocks [0,2048): 8 independent float4s per thread (MLP=8) for the
// masked feature copy (dead rows write-only; the row mask is a uniform load).
// Blocks [2048,2240): masked centers + cls_preds. Keep floats written above.
// ---------------------------------------------------------------------------
__global__ void __launch_bounds__(256) output_kernel(
    const float* __restrict__ features,
    const float* __restrict__ centers,
    const float* __restrict__ cls_preds,
    float* __restrict__ out)
{
    const int blk = blockIdx.x;
    const int t   = threadIdx.x;
    if (blk < 2048) {
        const float4* __restrict__ f4 = (const float4*)features;
        float4* __restrict__ o4 = (float4*)(out + OFF_FEAT);
        #pragma unroll
        for (int q = 0; q < 8; q++) {
            int i = blk*2048 + q*256 + t;       // covers BB*PP*CC/4 = 4,194,304
            int row = i >> 8;                   // 256 float4 per row
            float4 v = make_float4(0.f, 0.f, 0.f, 0.f);
            if (g_keep[row]) v = f4[i];
            o4[i] = v;
        }
    } else {
        const int i = (blk - 2048) * 256 + t;   // 0 .. BB*PP*3-1 exactly
        const int pt = i / 3;
        const float m = g_keep[pt] ? 1.f : 0.f;
        out[OFF_CTR + i] = m * centers[i];
        out[OFF_CLS + i] = m * cls_preds[i];
    }
}

extern "C" void kernel_launch(void* const* d_in, const int* in_sizes, int n_in,
                              void* d_out, int out_size)
{
    (void)in_sizes; (void)n_in; (void)out_size;
    const float* centers   = (const float*)d_in[0];
    const float* features  = (const float*)d_in[1];
    const float* cls_preds = (const float*)d_in[2];
    const float* radius    = (const float*)d_in[3];
    float* out = (float*)d_out;

    nms_all<<<NBK + NBK*NTILE, 512>>>(centers, cls_preds, radius, out);
    output_kernel<<<2048 + (BB*PP*3)/256, 256>>>(features, centers, cls_preds, out);
}